// round 6
// baseline (speedup 1.0000x reference)
#include <cuda_runtime.h>

// ---------------- problem constants ----------------
#define BB   128
#define SS   256
#define LL   200
#define DD   768
#define PD   50
#define FF   818             // D + 50
#define FP   832             // FF padded to mult of 16
#define RR   400
#define HH   150
#define NW   (BB * LL)       // 25600
#define POL  4
#define NTAG 5
#define N4   (4 * HH)        // 600
#define KBIP 160             // 151 padded (bias col at 150)
#define KTRI (LL * POL)      // 800
#define OUT_AP_OFF  0
#define OUT_OP_OFF  (NW * NTAG)
#define OUT_TRI_OFF (2 * NW * NTAG)

#define LDSA 260             // smem row stride for A tiles (256 + pad)
#define LDSB 68              // smem row stride for B tiles (64 + pad)

// packed f32x2 FMA: d.lo += a.lo*b.lo ; d.hi += a.hi*b.hi  (Blackwell FFMA2)
#define FMA_F32X2(d, a, b) \
    asm("fma.rn.f32x2 %0, %1, %2, %0;" : "+l"(d) : "l"(a), "l"(b))
#define DUP_F32X2(d, s) \
    asm("mov.b64 %0, {%1, %1};" : "=l"(d) : "r"(__float_as_uint(s)))
#define UNPK_F32X2(lo, hi, s) \
    asm("mov.b64 {%0, %1}, %2;" : "=f"(lo), "=f"(hi) : "l"(s))

// ---------------- scratch (__device__ globals are zero-initialized) ----------------
__device__ float g_h[NW * FP];          // pooled features, K padded   [25600, 832]
__device__ float g_reduc[NW * RR];      // reduc                       [25600, 400]
__device__ float g_rep[NW * N4];        // ap|op|ap2|op2 (relu'd)      [25600, 600]
__device__ float g_in1[NW * KBIP];      // [ap_node, 1, 0...]          [25600, 160]
__device__ float g_opn[NW * KBIP];      // [op_node, 0...]             [25600, 160]
__device__ float g_aff[NW * 4 * KBIP];  // affine, [w][p][160]         [25600, 640]
__device__ float g_Wcat[N4 * RR];       // packed head weights         [600, 400]
__device__ float g_bcat[N4];            // packed head biases          [600]
__device__ float g_Wr[RR * FP];         // W_reduc K-padded            [400, 832]
__device__ float g_Wbi[N4 * KBIP];      // W_bi K-padded               [600, 160]

// ---------------- pack weights (pad K dims, concat 4 heads) ----------------
__global__ void pack_kernel(const float* __restrict__ W_ap, const float* __restrict__ b_ap,
                            const float* __restrict__ W_op, const float* __restrict__ b_op,
                            const float* __restrict__ W_ap2, const float* __restrict__ b_ap2,
                            const float* __restrict__ W_op2, const float* __restrict__ b_op2,
                            const float* __restrict__ W_reduc, const float* __restrict__ W_bi) {
    int idx = blockIdx.x * blockDim.x + threadIdx.x;
    const int T0 = N4 * RR;
    const int T1 = T0 + N4;
    const int T2 = T1 + RR * FP;
    const int T3 = T2 + N4 * KBIP;
    if (idx < T0) {
        int n = idx / RR, k = idx - n * RR;
        const float* src; int nn = n;
        if (n < HH)          { src = W_ap;  }
        else if (n < 2 * HH) { src = W_op;  nn = n - HH; }
        else if (n < 3 * HH) { src = W_ap2; nn = n - 2 * HH; }
        else                 { src = W_op2; nn = n - 3 * HH; }
        g_Wcat[idx] = src[nn * RR + k];
    } else if (idx < T1) {
        int n = idx - T0;
        const float* src; int nn = n;
        if (n < HH)          { src = b_ap;  }
        else if (n < 2 * HH) { src = b_op;  nn = n - HH; }
        else if (n < 3 * HH) { src = b_ap2; nn = n - 2 * HH; }
        else                 { src = b_op2; nn = n - 3 * HH; }
        g_bcat[n] = src[nn];
    } else if (idx < T2) {
        int i = idx - T1;
        int n = i / FP, k = i - n * FP;
        g_Wr[i] = (k < FF) ? W_reduc[n * FF + k] : 0.f;
    } else if (idx < T3) {
        int i = idx - T2;
        int n = i / KBIP, k = i - n * KBIP;
        g_Wbi[i] = (k < HH + 1) ? W_bi[n * (HH + 1) + k] : 0.f;
    }
}

// set bias-1 column of in1 (pads stay zero from static init)
__global__ void init_kernel() {
    int w = blockIdx.x * blockDim.x + threadIdx.x;
    if (w < NW) g_in1[w * KBIP + HH] = 1.0f;
}

// ---------------- pool subwords (ragged mean) + concat pos embedding ----------------
__global__ void pool_kernel(const float* __restrict__ bert,
                            const int* __restrict__ positions,
                            const int* __restrict__ postag,
                            const float* __restrict__ embed) {
    int idx = blockIdx.x * blockDim.x + threadIdx.x;
    if (idx >= NW * FP) return;
    int w = idx / FP;
    int f = idx - w * FP;
    float v = 0.f;
    if (f < PD) {
        v = embed[postag[w] * PD + f];
    } else if (f < FF) {
        int d  = f - PD;
        int s0 = positions[2 * w];
        int s1 = positions[2 * w + 1];
        int b  = w / LL;
        const float* base = bert + ((long)b * SS) * DD + d;
        float s = 0.f;
        for (int t = s0; t <= s1; t++) s += base[(long)t * DD];
        v = s / (float)(s1 - s0 + 1);
    }
    g_h[idx] = v;
}

// ---------------- SGEMM-NT 256x64, BK=16, 256 thr, 16x4 microtile, FFMA2 core ----
// C[M,N] = A[M,K] * W[N,K]^T (+bias)(relu).  K % 16 == 0, lda/ldb % 4 == 0.
// Per thread: 16 consecutive rows (8 f32x2 pairs) x 4 consecutive cols.
// Inner kk: 4x LDS.128 (A, broadcast) + 1x LDS.128 (B) + 4 DUP + 32 FFMA2.
// OUTMODE: 0 plain, 1 also split-write ap_node->aux1 / op_node->aux2,
//          2 affine layout (C[w*640 + (n/150)*160 + n%150])
template<int RELU, int OUTMODE>
__global__ __launch_bounds__(256) void gemm_k(
    const float* __restrict__ A, int lda,
    const float* __restrict__ W, int ldb,
    float* __restrict__ C, int ldc,
    int M, int N, int K,
    const float* __restrict__ bias,
    float* __restrict__ aux1, float* __restrict__ aux2)
{
    __shared__ float As[2][16 * LDSA];
    __shared__ float Bs[2][16 * LDSB];
    const int tid = threadIdx.x;
    const int tx = tid & 15;           // N dim: 16 * 4
    const int ty = tid >> 4;           // M dim: 16 * 16
    const int rowBase = blockIdx.y * 256;
    const int colBase = blockIdx.x * 64;

    // A loader mapping: 4 rows per thread (lm, +64, +128, +192), 4 k's
    const int lm = tid >> 2;           // 0..63
    const int ak = (tid & 3) << 2;     // 0,4,8,12
    const int k4 = ak >> 2;
    // B loader mapping: 1 float4 per thread
    const int bm  = tid & 63;          // B row (C col) 0..63
    const int bk4 = tid >> 6;          // 0..3
    const int bk  = bk4 << 2;

    const long ar[4] = { rowBase + lm, rowBase + lm + 64,
                         rowBase + lm + 128, rowBase + lm + 192 };
    bool av[4];
    const float4* Ap[4];
    #pragma unroll
    for (int r = 0; r < 4; r++) {
        av[r] = ar[r] < M;
        Ap[r] = (const float4*)(A + ar[r] * lda);
    }
    const long brow = colBase + bm;
    const bool bv = brow < N;
    const float4* Bp = (const float4*)(W + brow * ldb);

    const float4 z4 = make_float4(0.f, 0.f, 0.f, 0.f);
    float4 ra[4], rbq;
    #pragma unroll
    for (int r = 0; r < 4; r++) ra[r] = av[r] ? Ap[r][k4] : z4;
    rbq = bv ? Bp[bk4] : z4;

    {
        float* as = As[0]; float* bs = Bs[0];
        #pragma unroll
        for (int r = 0; r < 4; r++) {
            as[(ak + 0) * LDSA + lm + 64 * r] = ra[r].x;
            as[(ak + 1) * LDSA + lm + 64 * r] = ra[r].y;
            as[(ak + 2) * LDSA + lm + 64 * r] = ra[r].z;
            as[(ak + 3) * LDSA + lm + 64 * r] = ra[r].w;
        }
        bs[(bk + 0) * LDSB + bm] = rbq.x;
        bs[(bk + 1) * LDSB + bm] = rbq.y;
        bs[(bk + 2) * LDSB + bm] = rbq.z;
        bs[(bk + 3) * LDSB + bm] = rbq.w;
    }
    __syncthreads();

    unsigned long long acc2[8][4];
    #pragma unroll
    for (int i = 0; i < 8; i++)
        #pragma unroll
        for (int j = 0; j < 4; j++) acc2[i][j] = 0ull;

    const int nt = K >> 4;
    for (int t = 0; t < nt; t++) {
        const int cur = t & 1;
        if (t + 1 < nt) {
            #pragma unroll
            for (int r = 0; r < 4; r++)
                ra[r] = av[r] ? Ap[r][((t + 1) << 2) + k4] : z4;
            rbq = bv ? Bp[((t + 1) << 2) + bk4] : z4;
        }
        const float* as = As[cur];
        const float* bs = Bs[cur];
        #pragma unroll
        for (int kk = 0; kk < 16; kk++) {
            const float* arow = as + kk * LDSA + ty * 16;
            ulonglong2 q0 = *(const ulonglong2*)(arow + 0);
            ulonglong2 q1 = *(const ulonglong2*)(arow + 4);
            ulonglong2 q2 = *(const ulonglong2*)(arow + 8);
            ulonglong2 q3 = *(const ulonglong2*)(arow + 12);
            float4 bq = *(const float4*)(bs + kk * LDSB + tx * 4);
            unsigned long long bd[4];
            DUP_F32X2(bd[0], bq.x);
            DUP_F32X2(bd[1], bq.y);
            DUP_F32X2(bd[2], bq.z);
            DUP_F32X2(bd[3], bq.w);
            unsigned long long a2[8] = { q0.x, q0.y, q1.x, q1.y,
                                         q2.x, q2.y, q3.x, q3.y };
            #pragma unroll
            for (int ip = 0; ip < 8; ip++)
                #pragma unroll
                for (int j = 0; j < 4; j++)
                    FMA_F32X2(acc2[ip][j], a2[ip], bd[j]);
        }
        if (t + 1 < nt) {
            float* asn = As[cur ^ 1]; float* bsn = Bs[cur ^ 1];
            #pragma unroll
            for (int r = 0; r < 4; r++) {
                asn[(ak + 0) * LDSA + lm + 64 * r] = ra[r].x;
                asn[(ak + 1) * LDSA + lm + 64 * r] = ra[r].y;
                asn[(ak + 2) * LDSA + lm + 64 * r] = ra[r].z;
                asn[(ak + 3) * LDSA + lm + 64 * r] = ra[r].w;
            }
            bsn[(bk + 0) * LDSB + bm] = rbq.x;
            bsn[(bk + 1) * LDSB + bm] = rbq.y;
            bsn[(bk + 2) * LDSB + bm] = rbq.z;
            bsn[(bk + 3) * LDSB + bm] = rbq.w;
        }
        __syncthreads();
    }

    #pragma unroll
    for (int ip = 0; ip < 8; ip++) {
        #pragma unroll
        for (int lane = 0; lane < 2; lane++) {
            int gm = rowBase + ty * 16 + 2 * ip + lane;
            if (gm >= M) continue;
            #pragma unroll
            for (int j = 0; j < 4; j++) {
                int gn = colBase + tx * 4 + j;
                if (gn >= N) continue;
                float lo, hi;
                UNPK_F32X2(lo, hi, acc2[ip][j]);
                float v = lane ? hi : lo;
                if (bias) v += bias[gn];
                if (RELU) v = fmaxf(v, 0.f);
                if (OUTMODE == 2) {
                    int p = gn / HH, h = gn - p * HH;
                    C[(long)gm * 4 * KBIP + p * KBIP + h] = v;
                } else {
                    C[(long)gm * ldc + gn] = v;
                    if (OUTMODE == 1) {
                        if (gn >= 300 && gn < 450)  aux1[(long)gm * KBIP + (gn - 300)] = v;
                        else if (gn >= 450)         aux2[(long)gm * KBIP + (gn - 450)] = v;
                    }
                }
            }
        }
    }
}

// ---------------- batched tri GEMM + transposed epilogue (FFMA2 core) ----------------
// per batch b: rows m (200, one 256-tile), cols gn = l1*4+p (800), K = 160 padded
__global__ __launch_bounds__(256) void tri_k(float* __restrict__ out) {
    __shared__ float As[2][16 * LDSA];
    __shared__ float Bs[2][16 * LDSB];
    const int tid = threadIdx.x;
    const int tx = tid & 15;
    const int ty = tid >> 4;
    const int colBase = blockIdx.x * 64;
    const int b = blockIdx.z;
    const long rb0 = (long)b * LL;

    const int lm = tid >> 2;
    const int ak = (tid & 3) << 2;
    const int k4 = ak >> 2;
    const int bm  = tid & 63;
    const int bk4 = tid >> 6;
    const int bk  = bk4 << 2;

    const int arr[4] = { lm, lm + 64, lm + 128, lm + 192 };
    bool av[4];
    const float4* Ap[4];
    #pragma unroll
    for (int r = 0; r < 4; r++) {
        av[r] = arr[r] < LL;
        Ap[r] = (const float4*)(g_opn + (rb0 + (av[r] ? arr[r] : 0)) * KBIP);
    }
    const int gnb = colBase + bm;
    const bool bv = gnb < KTRI;
    const float4* Bp = (const float4*)(g_aff + (rb0 + (bv ? (gnb >> 2) : 0)) * 4 * KBIP
                                       + (gnb & 3) * KBIP);

    const float4 z4 = make_float4(0.f, 0.f, 0.f, 0.f);
    float4 ra[4], rbq;
    #pragma unroll
    for (int r = 0; r < 4; r++) ra[r] = av[r] ? Ap[r][k4] : z4;
    rbq = bv ? Bp[bk4] : z4;

    {
        float* as = As[0]; float* bs = Bs[0];
        #pragma unroll
        for (int r = 0; r < 4; r++) {
            as[(ak + 0) * LDSA + lm + 64 * r] = ra[r].x;
            as[(ak + 1) * LDSA + lm + 64 * r] = ra[r].y;
            as[(ak + 2) * LDSA + lm + 64 * r] = ra[r].z;
            as[(ak + 3) * LDSA + lm + 64 * r] = ra[r].w;
        }
        bs[(bk + 0) * LDSB + bm] = rbq.x;
        bs[(bk + 1) * LDSB + bm] = rbq.y;
        bs[(bk + 2) * LDSB + bm] = rbq.z;
        bs[(bk + 3) * LDSB + bm] = rbq.w;
    }
    __syncthreads();

    unsigned long long acc2[8][4];
    #pragma unroll
    for (int i = 0; i < 8; i++)
        #pragma unroll
        for (int j = 0; j < 4; j++) acc2[i][j] = 0ull;

    const int nt = KBIP >> 4;   // 10
    for (int t = 0; t < nt; t++) {
        const int cur = t & 1;
        if (t + 1 < nt) {
            #pragma unroll
            for (int r = 0; r < 4; r++)
                ra[r] = av[r] ? Ap[r][((t + 1) << 2) + k4] : z4;
            rbq = bv ? Bp[((t + 1) << 2) + bk4] : z4;
        }
        const float* as = As[cur];
        const float* bs = Bs[cur];
        #pragma unroll
        for (int kk = 0; kk < 16; kk++) {
            const float* arow = as + kk * LDSA + ty * 16;
            ulonglong2 q0 = *(const ulonglong2*)(arow + 0);
            ulonglong2 q1 = *(const ulonglong2*)(arow + 4);
            ulonglong2 q2 = *(const ulonglong2*)(arow + 8);
            ulonglong2 q3 = *(const ulonglong2*)(arow + 12);
            float4 bq = *(const float4*)(bs + kk * LDSB + tx * 4);
            unsigned long long bd[4];
            DUP_F32X2(bd[0], bq.x);
            DUP_F32X2(bd[1], bq.y);
            DUP_F32X2(bd[2], bq.z);
            DUP_F32X2(bd[3], bq.w);
            unsigned long long a2[8] = { q0.x, q0.y, q1.x, q1.y,
                                         q2.x, q2.y, q3.x, q3.y };
            #pragma unroll
            for (int ip = 0; ip < 8; ip++)
                #pragma unroll
                for (int j = 0; j < 4; j++)
                    FMA_F32X2(acc2[ip][j], a2[ip], bd[j]);
        }
        if (t + 1 < nt) {
            float* asn = As[cur ^ 1]; float* bsn = Bs[cur ^ 1];
            #pragma unroll
            for (int r = 0; r < 4; r++) {
                asn[(ak + 0) * LDSA + lm + 64 * r] = ra[r].x;
                asn[(ak + 1) * LDSA + lm + 64 * r] = ra[r].y;
                asn[(ak + 2) * LDSA + lm + 64 * r] = ra[r].z;
                asn[(ak + 3) * LDSA + lm + 64 * r] = ra[r].w;
            }
            bsn[(bk + 0) * LDSB + bm] = rbq.x;
            bsn[(bk + 1) * LDSB + bm] = rbq.y;
            bsn[(bk + 2) * LDSB + bm] = rbq.z;
            bsn[(bk + 3) * LDSB + bm] = rbq.w;
        }
        __syncthreads();
    }

    #pragma unroll
    for (int ip = 0; ip < 8; ip++) {
        #pragma unroll
        for (int lane = 0; lane < 2; lane++) {
            int gm = ty * 16 + 2 * ip + lane;
            if (gm >= LL) continue;
            #pragma unroll
            for (int j = 0; j < 4; j++) {
                int gn = colBase + tx * 4 + j;
                if (gn >= KTRI) continue;
                float lo, hi;
                UNPK_F32X2(lo, hi, acc2[ip][j]);
                out[(long)OUT_TRI_OFF + (rb0 + gm) * KTRI + gn] = lane ? hi : lo;
            }
        }
    }
}

// ---------------- tag heads (tiny) ----------------
__global__ void tag_kernel(const float* __restrict__ W_aptag, const float* __restrict__ b_aptag,
                           const float* __restrict__ W_optag, const float* __restrict__ b_optag,
                           float* __restrict__ out) {
    int idx = blockIdx.x * blockDim.x + threadIdx.x;
    if (idx >= NW * 10) return;
    int w = idx / 10, t = idx - w * 10;
    const float* rep;
    const float* wv;
    float acc;
    int off;
    if (t < NTAG) {
        rep = g_rep + (long)w * N4;
        wv  = W_aptag + t * HH;
        acc = b_aptag[t];
        off = OUT_AP_OFF + w * NTAG + t;
    } else {
        int tt = t - NTAG;
        rep = g_rep + (long)w * N4 + HH;
        wv  = W_optag + tt * HH;
        acc = b_optag[tt];
        off = OUT_OP_OFF + w * NTAG + tt;
    }
    #pragma unroll 5
    for (int k = 0; k < HH; k++) acc += rep[k] * wv[k];
    out[off] = acc;
}

// ---------------- launch ----------------
extern "C" void kernel_launch(void* const* d_in, const int* in_sizes, int n_in,
                              void* d_out, int out_size) {
    const float* bert      = (const float*)d_in[0];
    const int*   positions = (const int*)  d_in[1];
    const int*   postag    = (const int*)  d_in[2];
    const float* embed     = (const float*)d_in[3];
    const float* W_reduc   = (const float*)d_in[4];
    const float* b_reduc   = (const float*)d_in[5];
    const float* W_ap      = (const float*)d_in[6];
    const float* b_ap      = (const float*)d_in[7];
    const float* W_op      = (const float*)d_in[8];
    const float* b_op      = (const float*)d_in[9];
    const float* W_ap2     = (const float*)d_in[10];
    const float* b_ap2     = (const float*)d_in[11];
    const float* W_op2     = (const float*)d_in[12];
    const float* b_op2     = (const float*)d_in[13];
    const float* W_aptag   = (const float*)d_in[14];
    const float* b_aptag   = (const float*)d_in[15];
    const float* W_optag   = (const float*)d_in[16];
    const float* b_optag   = (const float*)d_in[17];
    const float* W_bi      = (const float*)d_in[18];
    float* out = (float*)d_out;

    void* p;
    cudaGetSymbolAddress(&p, g_h);     float* ph     = (float*)p;
    cudaGetSymbolAddress(&p, g_reduc); float* preduc = (float*)p;
    cudaGetSymbolAddress(&p, g_rep);   float* prep   = (float*)p;
    cudaGetSymbolAddress(&p, g_in1);   float* pin1   = (float*)p;
    cudaGetSymbolAddress(&p, g_opn);   float* popn   = (float*)p;
    cudaGetSymbolAddress(&p, g_aff);   float* paff   = (float*)p;
    cudaGetSymbolAddress(&p, g_Wcat);  float* pWcat  = (float*)p;
    cudaGetSymbolAddress(&p, g_bcat);  float* pbcat  = (float*)p;
    cudaGetSymbolAddress(&p, g_Wr);    float* pWr    = (float*)p;
    cudaGetSymbolAddress(&p, g_Wbi);   float* pWbi   = (float*)p;

    // 1) pack weights + init bias column
    {
        int tot = N4 * RR + N4 + RR * FP + N4 * KBIP;
        pack_kernel<<<(tot + 255) / 256, 256>>>(W_ap, b_ap, W_op, b_op, W_ap2, b_ap2,
                                                W_op2, b_op2, W_reduc, W_bi);
        init_kernel<<<(NW + 255) / 256, 256>>>();
    }
    // 2) pool + concat (padded)
    {
        int tot = NW * FP;
        pool_kernel<<<(tot + 255) / 256, 256>>>(bert, positions, postag, embed);
    }
    // 3) reduc = h @ Wr^T + b_reduc   [25600,400], K=832
    {
        dim3 grid((RR + 63) / 64, NW / 256);
        gemm_k<0, 0><<<grid, 256>>>(ph, FP, pWr, FP, preduc, RR, NW, RR, FP,
                                    b_reduc, nullptr, nullptr);
    }
    // 4) rep = relu(reduc @ Wcat^T + bcat)  [25600,600], K=400; also writes in1/opn
    {
        dim3 grid((N4 + 63) / 64, NW / 256);
        gemm_k<1, 1><<<grid, 256>>>(preduc, RR, pWcat, RR, prep, N4, NW, N4, RR,
                                    pbcat, pin1, popn);
    }
    // 5) tag heads
    {
        int tot = NW * 10;
        tag_kernel<<<(tot + 255) / 256, 256>>>(W_aptag, b_aptag, W_optag, b_optag, out);
    }
    // 6) affine = in1 @ Wbi^T  [25600,600], K=160 (bias folded into col 150)
    {
        dim3 grid((N4 + 63) / 64, NW / 256);
        gemm_k<0, 2><<<grid, 256>>>(pin1, KBIP, pWbi, KBIP, paff, 0, NW, N4, KBIP,
                                    nullptr, nullptr, nullptr);
    }
    // 7) tri (batched) + transposed write
    {
        dim3 grid((KTRI + 63) / 64, 1, BB);
        tri_k<<<grid, 256>>>(out);
    }
}

// round 7
// speedup vs baseline: 1.2446x; 1.2446x over previous
#include <cuda_runtime.h>

// ---------------- problem constants ----------------
#define BB   128
#define SS   256
#define LL   200
#define DD   768
#define PD   50
#define FF   818             // D + 50
#define FP   832             // FF padded to mult of 16
#define RR   400
#define HH   150
#define NW   (BB * LL)       // 25600
#define POL  4
#define NTAG 5
#define N4   (4 * HH)        // 600
#define KBIP 160             // 151 padded (bias col at 150)
#define KTRI (LL * POL)      // 800
#define OUT_AP_OFF  0
#define OUT_OP_OFF  (NW * NTAG)
#define OUT_TRI_OFF (2 * NW * NTAG)

#define LDSA 132             // smem row stride for A tiles (128 + pad, 16B-aligned rows)
#define LDSB 68              // smem row stride for B tiles (64 + pad, 16B-aligned rows)

// packed f32x2 FMA: d.lo += a.lo*b.lo ; d.hi += a.hi*b.hi  (Blackwell FFMA2)
#define FMA_F32X2(d, a, b) \
    asm("fma.rn.f32x2 %0, %1, %2, %0;" : "+l"(d) : "l"(a), "l"(b))
#define DUP_F32X2(d, s) \
    asm("mov.b64 %0, {%1, %1};" : "=l"(d) : "r"(__float_as_uint(s)))
#define UNPK_F32X2(lo, hi, s) \
    asm("mov.b64 {%0, %1}, %2;" : "=f"(lo), "=f"(hi) : "l"(s))

// ---------------- scratch (__device__ globals are zero-initialized) ----------------
__device__ float g_h[NW * FP];          // pooled features, K padded   [25600, 832]
__device__ float g_reduc[NW * RR];      // reduc                       [25600, 400]
__device__ float g_rep[NW * N4];        // ap|op|ap2|op2 (relu'd)      [25600, 600]
__device__ float g_in1[NW * KBIP];      // [ap_node, 1, 0...]          [25600, 160]
__device__ float g_opn[NW * KBIP];      // [op_node, 0...]             [25600, 160]
__device__ float g_aff[NW * 4 * KBIP];  // affine, [w][p][160]         [25600, 640]
__device__ float g_Wcat[N4 * RR];       // packed head weights         [600, 400]
__device__ float g_bcat[N4];            // packed head biases          [600]
__device__ float g_Wr[RR * FP];         // W_reduc K-padded            [400, 832]
__device__ float g_Wbi[N4 * KBIP];      // W_bi K-padded               [600, 160]

// ---------------- pack weights (pad K dims, concat 4 heads) ----------------
__global__ void pack_kernel(const float* __restrict__ W_ap, const float* __restrict__ b_ap,
                            const float* __restrict__ W_op, const float* __restrict__ b_op,
                            const float* __restrict__ W_ap2, const float* __restrict__ b_ap2,
                            const float* __restrict__ W_op2, const float* __restrict__ b_op2,
                            const float* __restrict__ W_reduc, const float* __restrict__ W_bi) {
    int idx = blockIdx.x * blockDim.x + threadIdx.x;
    const int T0 = N4 * RR;
    const int T1 = T0 + N4;
    const int T2 = T1 + RR * FP;
    const int T3 = T2 + N4 * KBIP;
    if (idx < T0) {
        int n = idx / RR, k = idx - n * RR;
        const float* src; int nn = n;
        if (n < HH)          { src = W_ap;  }
        else if (n < 2 * HH) { src = W_op;  nn = n - HH; }
        else if (n < 3 * HH) { src = W_ap2; nn = n - 2 * HH; }
        else                 { src = W_op2; nn = n - 3 * HH; }
        g_Wcat[idx] = src[nn * RR + k];
    } else if (idx < T1) {
        int n = idx - T0;
        const float* src; int nn = n;
        if (n < HH)          { src = b_ap;  }
        else if (n < 2 * HH) { src = b_op;  nn = n - HH; }
        else if (n < 3 * HH) { src = b_ap2; nn = n - 2 * HH; }
        else                 { src = b_op2; nn = n - 3 * HH; }
        g_bcat[n] = src[nn];
    } else if (idx < T2) {
        int i = idx - T1;
        int n = i / FP, k = i - n * FP;
        g_Wr[i] = (k < FF) ? W_reduc[n * FF + k] : 0.f;
    } else if (idx < T3) {
        int i = idx - T2;
        int n = i / KBIP, k = i - n * KBIP;
        g_Wbi[i] = (k < HH + 1) ? W_bi[n * (HH + 1) + k] : 0.f;
    }
}

// set bias-1 column of in1 (pads stay zero from static init)
__global__ void init_kernel() {
    int w = blockIdx.x * blockDim.x + threadIdx.x;
    if (w < NW) g_in1[w * KBIP + HH] = 1.0f;
}

// ---------------- pool subwords (ragged mean) + concat pos embedding ----------------
__global__ void pool_kernel(const float* __restrict__ bert,
                            const int* __restrict__ positions,
                            const int* __restrict__ postag,
                            const float* __restrict__ embed) {
    int idx = blockIdx.x * blockDim.x + threadIdx.x;
    if (idx >= NW * FP) return;
    int w = idx / FP;
    int f = idx - w * FP;
    float v = 0.f;
    if (f < PD) {
        v = embed[postag[w] * PD + f];
    } else if (f < FF) {
        int d  = f - PD;
        int s0 = positions[2 * w];
        int s1 = positions[2 * w + 1];
        int b  = w / LL;
        const float* base = bert + ((long)b * SS) * DD + d;
        float s = 0.f;
        for (int t = s0; t <= s1; t++) s += base[(long)t * DD];
        v = s / (float)(s1 - s0 + 1);
    }
    g_h[idx] = v;
}

// ---------------- SGEMM-NT 128x64, BK=16, 256 thr, 8x4 microtile, FFMA2 core ----
// C[M,N] = A[M,K] * W[N,K]^T (+bias)(relu).  K % 16 == 0, lda/ldb % 4 == 0.
// Inner kk: 2x LDS.128 (A, broadcast) + 1x LDS.128 (B) + 4 DUP + 16 FFMA2.
// OUTMODE: 0 plain, 1 also split-write ap_node->aux1 / op_node->aux2,
//          2 affine layout (C[w*640 + (n/150)*160 + n%150])
template<int RELU, int OUTMODE>
__global__ __launch_bounds__(256) void gemm_k(
    const float* __restrict__ A, int lda,
    const float* __restrict__ W, int ldb,
    float* __restrict__ C, int ldc,
    int M, int N, int K,
    const float* __restrict__ bias,
    float* __restrict__ aux1, float* __restrict__ aux2)
{
    __shared__ float As[2][16 * LDSA];
    __shared__ float Bs[2][16 * LDSB];
    const int tid = threadIdx.x;
    const int tx = tid & 15;           // N dim: 16 * 4
    const int ty = tid >> 4;           // M dim: 16 * 8
    const int rowBase = blockIdx.y * 128;
    const int colBase = blockIdx.x * 64;

    const int lm = tid >> 2;           // 0..63
    const int ak = (tid & 3) << 2;     // 0,4,8,12
    const int k4 = ak >> 2;

    const long arow0 = rowBase + lm;
    const long arow1 = rowBase + lm + 64;
    const long brow  = colBase + lm;
    const bool av0 = arow0 < M;
    const bool av1 = arow1 < M;
    const bool bv  = brow < N;

    const float4* Ap0 = (const float4*)(A + arow0 * lda);
    const float4* Ap1 = (const float4*)(A + arow1 * lda);
    const float4* Bp  = (const float4*)(W + brow * ldb);

    const float4 z4 = make_float4(0.f, 0.f, 0.f, 0.f);
    float4 ra0 = av0 ? Ap0[k4] : z4;
    float4 ra1 = av1 ? Ap1[k4] : z4;
    float4 rb  = bv  ? Bp[k4]  : z4;

    {
        float* as = As[0]; float* bs = Bs[0];
        as[(ak + 0) * LDSA + lm] = ra0.x;
        as[(ak + 1) * LDSA + lm] = ra0.y;
        as[(ak + 2) * LDSA + lm] = ra0.z;
        as[(ak + 3) * LDSA + lm] = ra0.w;
        as[(ak + 0) * LDSA + lm + 64] = ra1.x;
        as[(ak + 1) * LDSA + lm + 64] = ra1.y;
        as[(ak + 2) * LDSA + lm + 64] = ra1.z;
        as[(ak + 3) * LDSA + lm + 64] = ra1.w;
        bs[(ak + 0) * LDSB + lm] = rb.x;
        bs[(ak + 1) * LDSB + lm] = rb.y;
        bs[(ak + 2) * LDSB + lm] = rb.z;
        bs[(ak + 3) * LDSB + lm] = rb.w;
    }
    __syncthreads();

    unsigned long long acc2[4][4];
    #pragma unroll
    for (int i = 0; i < 4; i++)
        #pragma unroll
        for (int j = 0; j < 4; j++) acc2[i][j] = 0ull;

    const int nt = K >> 4;
    for (int t = 0; t < nt; t++) {
        const int cur = t & 1;
        if (t + 1 < nt) {
            int idx = ((t + 1) << 2) + k4;
            ra0 = av0 ? Ap0[idx] : z4;
            ra1 = av1 ? Ap1[idx] : z4;
            rb  = bv  ? Bp[idx]  : z4;
        }
        const float* as = As[cur];
        const float* bs = Bs[cur];
        #pragma unroll
        for (int kk = 0; kk < 16; kk++) {
            const float* arow = as + kk * LDSA + ty * 8;
            ulonglong2 q0 = *(const ulonglong2*)(arow + 0);   // rows 0-3 (2 f32x2)
            ulonglong2 q1 = *(const ulonglong2*)(arow + 4);   // rows 4-7
            float4 bq = *(const float4*)(bs + kk * LDSB + tx * 4);
            unsigned long long bd[4];
            DUP_F32X2(bd[0], bq.x);
            DUP_F32X2(bd[1], bq.y);
            DUP_F32X2(bd[2], bq.z);
            DUP_F32X2(bd[3], bq.w);
            unsigned long long a2[4] = { q0.x, q0.y, q1.x, q1.y };
            #pragma unroll
            for (int ip = 0; ip < 4; ip++)
                #pragma unroll
                for (int j = 0; j < 4; j++)
                    FMA_F32X2(acc2[ip][j], a2[ip], bd[j]);
        }
        if (t + 1 < nt) {
            float* asn = As[cur ^ 1]; float* bsn = Bs[cur ^ 1];
            asn[(ak + 0) * LDSA + lm] = ra0.x;
            asn[(ak + 1) * LDSA + lm] = ra0.y;
            asn[(ak + 2) * LDSA + lm] = ra0.z;
            asn[(ak + 3) * LDSA + lm] = ra0.w;
            asn[(ak + 0) * LDSA + lm + 64] = ra1.x;
            asn[(ak + 1) * LDSA + lm + 64] = ra1.y;
            asn[(ak + 2) * LDSA + lm + 64] = ra1.z;
            asn[(ak + 3) * LDSA + lm + 64] = ra1.w;
            bsn[(ak + 0) * LDSB + lm] = rb.x;
            bsn[(ak + 1) * LDSB + lm] = rb.y;
            bsn[(ak + 2) * LDSB + lm] = rb.z;
            bsn[(ak + 3) * LDSB + lm] = rb.w;
        }
        __syncthreads();
    }

    #pragma unroll
    for (int ip = 0; ip < 4; ip++) {
        #pragma unroll
        for (int lane = 0; lane < 2; lane++) {
            int gm = rowBase + ty * 8 + 2 * ip + lane;
            if (gm >= M) continue;
            #pragma unroll
            for (int j = 0; j < 4; j++) {
                int gn = colBase + tx * 4 + j;
                if (gn >= N) continue;
                float lo, hi;
                UNPK_F32X2(lo, hi, acc2[ip][j]);
                float v = lane ? hi : lo;
                if (bias) v += bias[gn];
                if (RELU) v = fmaxf(v, 0.f);
                if (OUTMODE == 2) {
                    int p = gn / HH, h = gn - p * HH;
                    C[(long)gm * 4 * KBIP + p * KBIP + h] = v;
                } else {
                    C[(long)gm * ldc + gn] = v;
                    if (OUTMODE == 1) {
                        if (gn >= 300 && gn < 450)  aux1[(long)gm * KBIP + (gn - 300)] = v;
                        else if (gn >= 450)         aux2[(long)gm * KBIP + (gn - 450)] = v;
                    }
                }
            }
        }
    }
}

// ---------------- batched tri GEMM + transposed epilogue (FFMA2 core) ----------------
// per batch b: rows m (200), cols gn = l1*4+p (800), K = 160 (padded; opn pads are 0)
__global__ __launch_bounds__(256) void tri_k(float* __restrict__ out) {
    __shared__ float As[2][16 * LDSA];
    __shared__ float Bs[2][16 * LDSB];
    const int tid = threadIdx.x;
    const int tx = tid & 15;
    const int ty = tid >> 4;
    const int rowBase = blockIdx.y * 128;
    const int colBase = blockIdx.x * 64;
    const int b = blockIdx.z;
    const long rb0 = (long)b * LL;

    const int lm = tid >> 2;
    const int ak = (tid & 3) << 2;
    const int k4 = ak >> 2;

    const int arow0 = rowBase + lm;
    const int arow1 = rowBase + lm + 64;
    const int gnb   = colBase + lm;
    const bool av0 = arow0 < LL;
    const bool av1 = arow1 < LL;
    const bool bv  = gnb < KTRI;

    const float4* Ap0 = (const float4*)(g_opn + (rb0 + (av0 ? arow0 : 0)) * KBIP);
    const float4* Ap1 = (const float4*)(g_opn + (rb0 + (av1 ? arow1 : 0)) * KBIP);
    const float4* Bp  = (const float4*)(g_aff + (rb0 + (bv ? (gnb >> 2) : 0)) * 4 * KBIP
                                        + (gnb & 3) * KBIP);

    const float4 z4 = make_float4(0.f, 0.f, 0.f, 0.f);
    float4 ra0 = av0 ? Ap0[k4] : z4;
    float4 ra1 = av1 ? Ap1[k4] : z4;
    float4 rb  = bv  ? Bp[k4]  : z4;

    {
        float* as = As[0]; float* bs = Bs[0];
        as[(ak + 0) * LDSA + lm] = ra0.x;
        as[(ak + 1) * LDSA + lm] = ra0.y;
        as[(ak + 2) * LDSA + lm] = ra0.z;
        as[(ak + 3) * LDSA + lm] = ra0.w;
        as[(ak + 0) * LDSA + lm + 64] = ra1.x;
        as[(ak + 1) * LDSA + lm + 64] = ra1.y;
        as[(ak + 2) * LDSA + lm + 64] = ra1.z;
        as[(ak + 3) * LDSA + lm + 64] = ra1.w;
        bs[(ak + 0) * LDSB + lm] = rb.x;
        bs[(ak + 1) * LDSB + lm] = rb.y;
        bs[(ak + 2) * LDSB + lm] = rb.z;
        bs[(ak + 3) * LDSB + lm] = rb.w;
    }
    __syncthreads();

    unsigned long long acc2[4][4];
    #pragma unroll
    for (int i = 0; i < 4; i++)
        #pragma unroll
        for (int j = 0; j < 4; j++) acc2[i][j] = 0ull;

    const int nt = KBIP >> 4;   // 10
    for (int t = 0; t < nt; t++) {
        const int cur = t & 1;
        if (t + 1 < nt) {
            int idx = ((t + 1) << 2) + k4;
            ra0 = av0 ? Ap0[idx] : z4;
            ra1 = av1 ? Ap1[idx] : z4;
            rb  = bv  ? Bp[idx]  : z4;
        }
        const float* as = As[cur];
        const float* bs = Bs[cur];
        #pragma unroll
        for (int kk = 0; kk < 16; kk++) {
            const float* arow = as + kk * LDSA + ty * 8;
            ulonglong2 q0 = *(const ulonglong2*)(arow + 0);
            ulonglong2 q1 = *(const ulonglong2*)(arow + 4);
            float4 bq = *(const float4*)(bs + kk * LDSB + tx * 4);
            unsigned long long bd[4];
            DUP_F32X2(bd[0], bq.x);
            DUP_F32X2(bd[1], bq.y);
            DUP_F32X2(bd[2], bq.z);
            DUP_F32X2(bd[3], bq.w);
            unsigned long long a2[4] = { q0.x, q0.y, q1.x, q1.y };
            #pragma unroll
            for (int ip = 0; ip < 4; ip++)
                #pragma unroll
                for (int j = 0; j < 4; j++)
                    FMA_F32X2(acc2[ip][j], a2[ip], bd[j]);
        }
        if (t + 1 < nt) {
            float* asn = As[cur ^ 1]; float* bsn = Bs[cur ^ 1];
            asn[(ak + 0) * LDSA + lm] = ra0.x;
            asn[(ak + 1) * LDSA + lm] = ra0.y;
            asn[(ak + 2) * LDSA + lm] = ra0.z;
            asn[(ak + 3) * LDSA + lm] = ra0.w;
            asn[(ak + 0) * LDSA + lm + 64] = ra1.x;
            asn[(ak + 1) * LDSA + lm + 64] = ra1.y;
            asn[(ak + 2) * LDSA + lm + 64] = ra1.z;
            asn[(ak + 3) * LDSA + lm + 64] = ra1.w;
            bsn[(ak + 0) * LDSB + lm] = rb.x;
            bsn[(ak + 1) * LDSB + lm] = rb.y;
            bsn[(ak + 2) * LDSB + lm] = rb.z;
            bsn[(ak + 3) * LDSB + lm] = rb.w;
        }
        __syncthreads();
    }

    #pragma unroll
    for (int ip = 0; ip < 4; ip++) {
        #pragma unroll
        for (int lane = 0; lane < 2; lane++) {
            int gm = rowBase + ty * 8 + 2 * ip + lane;
            if (gm >= LL) continue;
            #pragma unroll
            for (int j = 0; j < 4; j++) {
                int gn = colBase + tx * 4 + j;
                if (gn >= KTRI) continue;
                float lo, hi;
                UNPK_F32X2(lo, hi, acc2[ip][j]);
                out[(long)OUT_TRI_OFF + (rb0 + gm) * KTRI + gn] = lane ? hi : lo;
            }
        }
    }
}

// ---------------- tag heads (tiny) ----------------
__global__ void tag_kernel(const float* __restrict__ W_aptag, const float* __restrict__ b_aptag,
                           const float* __restrict__ W_optag, const float* __restrict__ b_optag,
                           float* __restrict__ out) {
    int idx = blockIdx.x * blockDim.x + threadIdx.x;
    if (idx >= NW * 10) return;
    int w = idx / 10, t = idx - w * 10;
    const float* rep;
    const float* wv;
    float acc;
    int off;
    if (t < NTAG) {
        rep = g_rep + (long)w * N4;
        wv  = W_aptag + t * HH;
        acc = b_aptag[t];
        off = OUT_AP_OFF + w * NTAG + t;
    } else {
        int tt = t - NTAG;
        rep = g_rep + (long)w * N4 + HH;
        wv  = W_optag + tt * HH;
        acc = b_optag[tt];
        off = OUT_OP_OFF + w * NTAG + tt;
    }
    #pragma unroll 5
    for (int k = 0; k < HH; k++) acc += rep[k] * wv[k];
    out[off] = acc;
}

// ---------------- launch ----------------
extern "C" void kernel_launch(void* const* d_in, const int* in_sizes, int n_in,
                              void* d_out, int out_size) {
    const float* bert      = (const float*)d_in[0];
    const int*   positions = (const int*)  d_in[1];
    const int*   postag    = (const int*)  d_in[2];
    const float* embed     = (const float*)d_in[3];
    const float* W_reduc   = (const float*)d_in[4];
    const float* b_reduc   = (const float*)d_in[5];
    const float* W_ap      = (const float*)d_in[6];
    const float* b_ap      = (const float*)d_in[7];
    const float* W_op      = (const float*)d_in[8];
    const float* b_op      = (const float*)d_in[9];
    const float* W_ap2     = (const float*)d_in[10];
    const float* b_ap2     = (const float*)d_in[11];
    const float* W_op2     = (const float*)d_in[12];
    const float* b_op2     = (const float*)d_in[13];
    const float* W_aptag   = (const float*)d_in[14];
    const float* b_aptag   = (const float*)d_in[15];
    const float* W_optag   = (const float*)d_in[16];
    const float* b_optag   = (const float*)d_in[17];
    const float* W_bi      = (const float*)d_in[18];
    float* out = (float*)d_out;

    void* p;
    cudaGetSymbolAddress(&p, g_h);     float* ph     = (float*)p;
    cudaGetSymbolAddress(&p, g_reduc); float* preduc = (float*)p;
    cudaGetSymbolAddress(&p, g_rep);   float* prep   = (float*)p;
    cudaGetSymbolAddress(&p, g_in1);   float* pin1   = (float*)p;
    cudaGetSymbolAddress(&p, g_opn);   float* popn   = (float*)p;
    cudaGetSymbolAddress(&p, g_aff);   float* paff   = (float*)p;
    cudaGetSymbolAddress(&p, g_Wcat);  float* pWcat  = (float*)p;
    cudaGetSymbolAddress(&p, g_bcat);  float* pbcat  = (float*)p;
    cudaGetSymbolAddress(&p, g_Wr);    float* pWr    = (float*)p;
    cudaGetSymbolAddress(&p, g_Wbi);   float* pWbi   = (float*)p;

    // 1) pack weights + init bias column
    {
        int tot = N4 * RR + N4 + RR * FP + N4 * KBIP;
        pack_kernel<<<(tot + 255) / 256, 256>>>(W_ap, b_ap, W_op, b_op, W_ap2, b_ap2,
                                                W_op2, b_op2, W_reduc, W_bi);
        init_kernel<<<(NW + 255) / 256, 256>>>();
    }
    // 2) pool + concat (padded)
    {
        int tot = NW * FP;
        pool_kernel<<<(tot + 255) / 256, 256>>>(bert, positions, postag, embed);
    }
    // 3) reduc = h @ Wr^T + b_reduc   [25600,400], K=832
    {
        dim3 grid((RR + 63) / 64, NW / 128);
        gemm_k<0, 0><<<grid, 256>>>(ph, FP, pWr, FP, preduc, RR, NW, RR, FP,
                                    b_reduc, nullptr, nullptr);
    }
    // 4) rep = relu(reduc @ Wcat^T + bcat)  [25600,600], K=400; also writes in1/opn
    {
        dim3 grid((N4 + 63) / 64, NW / 128);
        gemm_k<1, 1><<<grid, 256>>>(preduc, RR, pWcat, RR, prep, N4, NW, N4, RR,
                                    pbcat, pin1, popn);
    }
    // 5) tag heads
    {
        int tot = NW * 10;
        tag_kernel<<<(tot + 255) / 256, 256>>>(W_aptag, b_aptag, W_optag, b_optag, out);
    }
    // 6) affine = in1 @ Wbi^T  [25600,600], K=160 (bias folded into col 150)
    {
        dim3 grid((N4 + 63) / 64, NW / 128);
        gemm_k<0, 2><<<grid, 256>>>(pin1, KBIP, pWbi, KBIP, paff, 0, NW, N4, KBIP,
                                    nullptr, nullptr, nullptr);
    }
    // 7) tri (batched) + transposed write
    {
        dim3 grid((KTRI + 63) / 64, (LL + 127) / 128, BB);
        tri_k<<<grid, 256>>>(out);
    }
}

// round 9
// speedup vs baseline: 1.7170x; 1.3795x over previous
#include <cuda_runtime.h>
#include <cuda_bf16.h>
#include <cstdint>

// ---------------- problem constants ----------------
#define BB   128
#define SS   256
#define LL   200
#define DD   768
#define PD   50
#define FF   818
#define FP   832             // gemm1 K (padded)
#define RR   400
#define KR2  448             // gemm2 K padded
#define HH   150
#define NW   (BB * LL)       // 25600
#define NTAG 5
#define N4   600
#define KBI2 192             // affine/tri K padded (151 -> 192)
#define KTRI 800
#define OUT_AP_OFF  0
#define OUT_OP_OFF  (NW * NTAG)
#define OUT_TRI_OFF (2 * NW * NTAG)

typedef __nv_bfloat16 bf16;

// ---------------- scratch (__device__ globals, zero-init) ----------------
__device__ bf16  g_hh[NW * FP],  g_hl[NW * FP];
__device__ bf16  g_rdh[NW * KR2], g_rdl[NW * KR2];
__device__ float g_rep[NW * N4];
__device__ bf16  g_i1h[NW * KBI2], g_i1l[NW * KBI2];
__device__ bf16  g_onh[NW * KBI2], g_onl[NW * KBI2];
__device__ bf16  g_afh[NW * 4 * KBI2], g_afl[NW * 4 * KBI2];
__device__ bf16  g_Wrh[RR * FP],  g_Wrl[RR * FP];
__device__ bf16  g_Wch[N4 * KR2], g_Wcl[N4 * KR2];
__device__ bf16  g_Wbh[N4 * KBI2], g_Wbl[N4 * KBI2];
__device__ float g_bcat[N4];

__device__ __forceinline__ void bsplit(float v, bf16* ph, bf16* pl) {
    bf16 h = __float2bfloat16(v);
    *ph = h;
    *pl = __float2bfloat16(v - __bfloat162float(h));
}

// ---------------- PTX helpers (all baseline sm_80+ features) ----------------
__device__ __forceinline__ uint32_t sm_u32(const void* p) {
    uint32_t a;
    asm("{ .reg .u64 t; cvta.to.shared.u64 t, %1; cvt.u32.u64 %0, t; }" : "=r"(a) : "l"(p));
    return a;
}

#define CP16(dst, src) \
    asm volatile("cp.async.cg.shared.global [%0], [%1], 16;" :: "r"(dst), "l"(src) : "memory")
#define CP_COMMIT() asm volatile("cp.async.commit_group;" ::: "memory")
#define CP_WAIT1()  asm volatile("cp.async.wait_group 1;" ::: "memory")
#define CP_WAIT0()  asm volatile("cp.async.wait_group 0;" ::: "memory")

#define LDSM4(r0, r1, r2, r3, addr) \
    asm volatile("ldmatrix.sync.aligned.m8n8.x4.shared.b16 {%0,%1,%2,%3}, [%4];" \
                 : "=r"(r0), "=r"(r1), "=r"(r2), "=r"(r3) : "r"(addr))

#define MMA16816(d, a0, a1, a2, a3, b0, b1) \
    asm volatile("mma.sync.aligned.m16n8k16.row.col.f32.bf16.bf16.f32 " \
                 "{%0,%1,%2,%3}, {%4,%5,%6,%7}, {%8,%9}, {%0,%1,%2,%3};" \
                 : "+f"((d)[0]), "+f"((d)[1]), "+f"((d)[2]), "+f"((d)[3]) \
                 : "r"(a0), "r"(a1), "r"(a2), "r"(a3), "r"(b0), "r"(b1))

// smem stage layout (bytes): A 128x32 bf16 (stride 40 bf16 = 80B), B 64x32 bf16
#define S_AH    0
#define S_AL    10240
#define S_BH    20480
#define S_BL    25600
#define S_STAGE 30720
#define SMEM_SZ (2 * S_STAGE)    // 61440

// ---------------- HMMA GEMM: C[M,N] = (Ahi+Alo)[M,K] * (Bhi+Blo)[N,K]^T ----
// 128x64 block tile, 8 warps (4Mx2N), warp tile 32x32, BK=32, cp.async dbl-buffer.
// MODE 0: +bias -> reduc hi/lo;  MODE 1: relu(+bias) -> g_rep + in1/opn splits;
// MODE 2: -> aff hi/lo;          MODE 3: batched (z) -> out triplet.
template<int MODE>
__global__ __launch_bounds__(256, 2) void mma_gemm(
    const bf16* __restrict__ Ahi, const bf16* __restrict__ Alo, int lda, long aStride,
    const bf16* __restrict__ Bhi, const bf16* __restrict__ Blo, int ldb, long bStride,
    int M, int N, int nchunk,
    const float* __restrict__ bias, float* __restrict__ out)
{
    extern __shared__ char smem[];
    const uint32_t sbase = sm_u32(smem);
    const int tid = threadIdx.x;
    const int lane = tid & 31;
    const int warp = tid >> 5;
    const int warpM = warp >> 1;       // 0..3
    const int warpN = warp & 1;        // 0..1
    const int rowBase = blockIdx.y * 128;
    const int colBase = blockIdx.x * 64;
    const int z = blockIdx.z;

    const bf16* ahi = Ahi + (long)z * aStride;
    const bf16* alo = Alo + (long)z * aStride;
    const bf16* bhi = Bhi + (long)z * bStride;
    const bf16* blo = Blo + (long)z * bStride;

    // loader mapping
    const int lrow = tid >> 2;         // 0..63
    const int lc8  = tid & 3;          // 16B chunk within 64B row-chunk

    // ldmatrix per-lane offsets
    const int a_row = (lane & 7) + ((lane >> 3) & 1) * 8;
    const int a_kh  = lane >> 4;
    const uint32_t aoff = (uint32_t)((warpM * 32 + a_row) * 80 + a_kh * 16);
    const int b_n  = (lane & 7) + (lane >> 4) * 8;
    const int b_kh = (lane >> 3) & 1;
    const uint32_t boff = (uint32_t)((warpN * 32 + b_n) * 80 + b_kh * 16);

    float acc[2][4][4];
    #pragma unroll
    for (int m = 0; m < 2; m++)
        #pragma unroll
        for (int t = 0; t < 4; t++)
            #pragma unroll
            for (int r = 0; r < 4; r++) acc[m][t][r] = 0.f;

    // ---- async copy of one K-chunk (32 bf16) into buffer ----
    auto issue = [&](int c) {
        const uint32_t bufb = sbase + (c & 1) * S_STAGE;
        const int kof = c * 32 + lc8 * 8;
        #pragma unroll
        for (int t = 0; t < 2; t++) {
            int row = lrow + t * 64;
            long gr = rowBase + row; if (gr > M - 1) gr = M - 1;
            uint32_t d = bufb + row * 80 + lc8 * 16;
            CP16(d + S_AH, ahi + gr * (long)lda + kof);
            CP16(d + S_AL, alo + gr * (long)lda + kof);
        }
        {
            long gn = colBase + lrow; if (gn > N - 1) gn = N - 1;
            uint32_t d = bufb + lrow * 80 + lc8 * 16;
            CP16(d + S_BH, bhi + gn * (long)ldb + kof);
            CP16(d + S_BL, blo + gn * (long)ldb + kof);
        }
        CP_COMMIT();
    };

    issue(0);
    for (int c = 0; c < nchunk; c++) {
        if (c + 1 < nchunk) { issue(c + 1); CP_WAIT1(); }
        else                { CP_WAIT0(); }
        __syncthreads();

        const uint32_t bb = sbase + (c & 1) * S_STAGE;
        #pragma unroll
        for (int k16 = 0; k16 < 2; k16++) {
            const uint32_t ka = bb + k16 * 32 + aoff;
            const uint32_t kb = bb + k16 * 32 + boff;
            uint32_t ah[8], al[8], bh[8], bl[8];
            LDSM4(ah[0], ah[1], ah[2], ah[3], ka + S_AH);
            LDSM4(ah[4], ah[5], ah[6], ah[7], ka + S_AH + 16 * 80);
            LDSM4(al[0], al[1], al[2], al[3], ka + S_AL);
            LDSM4(al[4], al[5], al[6], al[7], ka + S_AL + 16 * 80);
            LDSM4(bh[0], bh[1], bh[2], bh[3], kb + S_BH);
            LDSM4(bh[4], bh[5], bh[6], bh[7], kb + S_BH + 16 * 80);
            LDSM4(bl[0], bl[1], bl[2], bl[3], kb + S_BL);
            LDSM4(bl[4], bl[5], bl[6], bl[7], kb + S_BL + 16 * 80);
            #pragma unroll
            for (int m = 0; m < 2; m++) {
                #pragma unroll
                for (int t8 = 0; t8 < 4; t8++) {
                    int g = t8 >> 1, s = t8 & 1;
                    uint32_t bh0 = bh[g * 4 + s * 2], bh1 = bh[g * 4 + s * 2 + 1];
                    uint32_t bl0 = bl[g * 4 + s * 2], bl1 = bl[g * 4 + s * 2 + 1];
                    MMA16816(acc[m][t8], ah[m*4], ah[m*4+1], ah[m*4+2], ah[m*4+3], bh0, bh1);
                    MMA16816(acc[m][t8], ah[m*4], ah[m*4+1], ah[m*4+2], ah[m*4+3], bl0, bl1);
                    MMA16816(acc[m][t8], al[m*4], al[m*4+1], al[m*4+2], al[m*4+3], bh0, bh1);
                }
            }
        }
        __syncthreads();
    }

    // ---- epilogue ----
    const int lr = lane >> 2;
    const int lc = (lane & 3) * 2;
    #pragma unroll
    for (int m = 0; m < 2; m++) {
        #pragma unroll
        for (int t8 = 0; t8 < 4; t8++) {
            #pragma unroll
            for (int ri = 0; ri < 4; ri++) {
                int gm = rowBase + warpM * 32 + m * 16 + lr + ((ri & 2) ? 8 : 0);
                int gn = colBase + warpN * 32 + t8 * 8 + lc + (ri & 1);
                if (gm >= M || gn >= N) continue;
                float v = acc[m][t8][ri];
                if (MODE == 0) {
                    v += bias[gn];
                    bsplit(v, &g_rdh[(long)gm * KR2 + gn], &g_rdl[(long)gm * KR2 + gn]);
                } else if (MODE == 1) {
                    v = fmaxf(v + bias[gn], 0.f);
                    g_rep[(long)gm * N4 + gn] = v;
                    if (gn >= 300 && gn < 450)
                        bsplit(v, &g_i1h[(long)gm * KBI2 + gn - 300],
                                  &g_i1l[(long)gm * KBI2 + gn - 300]);
                    else if (gn >= 450)
                        bsplit(v, &g_onh[(long)gm * KBI2 + gn - 450],
                                  &g_onl[(long)gm * KBI2 + gn - 450]);
                } else if (MODE == 2) {
                    int p = gn / HH, h = gn - p * HH;
                    long o = ((long)gm * 4 + p) * KBI2 + h;
                    bsplit(v, &g_afh[o], &g_afl[o]);
                } else {
                    out[(long)OUT_TRI_OFF + ((long)z * LL + gm) * KTRI + gn] = v;
                }
            }
        }
    }
}

// ---------------- pack weights into bf16 hi/lo (padded K) ----------------
__global__ void pack_kernel(const float* __restrict__ W_ap, const float* __restrict__ b_ap,
                            const float* __restrict__ W_op, const float* __restrict__ b_op,
                            const float* __restrict__ W_ap2, const float* __restrict__ b_ap2,
                            const float* __restrict__ W_op2, const float* __restrict__ b_op2,
                            const float* __restrict__ W_reduc, const float* __restrict__ W_bi) {
    int idx = blockIdx.x * blockDim.x + threadIdx.x;
    const int T0 = RR * FP;
    const int T1 = T0 + N4 * KR2;
    const int T2 = T1 + N4 * KBI2;
    const int T3 = T2 + N4;
    if (idx < T0) {
        int n = idx / FP, k = idx - n * FP;
        float v = (k < FF) ? W_reduc[n * FF + k] : 0.f;
        bsplit(v, &g_Wrh[idx], &g_Wrl[idx]);
    } else if (idx < T1) {
        int i = idx - T0;
        int n = i / KR2, k = i - n * KR2;
        float v = 0.f;
        if (k < RR) {
            const float* src; int nn = n;
            if (n < HH)          { src = W_ap;  }
            else if (n < 2 * HH) { src = W_op;  nn = n - HH; }
            else if (n < 3 * HH) { src = W_ap2; nn = n - 2 * HH; }
            else                 { src = W_op2; nn = n - 3 * HH; }
            v = src[nn * RR + k];
        }
        bsplit(v, &g_Wch[i], &g_Wcl[i]);
    } else if (idx < T2) {
        int i = idx - T1;
        int n = i / KBI2, k = i - n * KBI2;
        float v = (k < HH + 1) ? W_bi[n * (HH + 1) + k] : 0.f;
        bsplit(v, &g_Wbh[i], &g_Wbl[i]);
    } else if (idx < T3) {
        int n = idx - T2;
        const float* src; int nn = n;
        if (n < HH)          { src = b_ap;  }
        else if (n < 2 * HH) { src = b_op;  nn = n - HH; }
        else if (n < 3 * HH) { src = b_ap2; nn = n - 2 * HH; }
        else                 { src = b_op2; nn = n - 3 * HH; }
        g_bcat[n] = src[nn];
    }
}

// set bias-1 column of in1
__global__ void init_kernel() {
    int w = blockIdx.x * blockDim.x + threadIdx.x;
    if (w < NW) {
        g_i1h[(long)w * KBI2 + HH] = __float2bfloat16(1.0f);
        g_i1l[(long)w * KBI2 + HH] = __float2bfloat16(0.0f);
    }
}

// ---------------- pool subwords + concat pos embedding -> bf16 hi/lo ----------------
__global__ void pool_kernel(const float* __restrict__ bert,
                            const int* __restrict__ positions,
                            const int* __restrict__ postag,
                            const float* __restrict__ embed) {
    int idx = blockIdx.x * blockDim.x + threadIdx.x;
    if (idx >= NW * FP) return;
    int w = idx / FP;
    int f = idx - w * FP;
    float v = 0.f;
    if (f < PD) {
        v = embed[postag[w] * PD + f];
    } else if (f < FF) {
        int d  = f - PD;
        int s0 = positions[2 * w];
        int s1 = positions[2 * w + 1];
        int b  = w / LL;
        const float* base = bert + ((long)b * SS) * DD + d;
        float s = 0.f;
        for (int t = s0; t <= s1; t++) s += base[(long)t * DD];
        v = s / (float)(s1 - s0 + 1);
    }
    bsplit(v, &g_hh[idx], &g_hl[idx]);
}

// ---------------- tag heads (tiny) ----------------
__global__ void tag_kernel(const float* __restrict__ W_aptag, const float* __restrict__ b_aptag,
                           const float* __restrict__ W_optag, const float* __restrict__ b_optag,
                           float* __restrict__ out) {
    int idx = blockIdx.x * blockDim.x + threadIdx.x;
    if (idx >= NW * 10) return;
    int w = idx / 10, t = idx - w * 10;
    const float* rep;
    const float* wv;
    float acc;
    int off;
    if (t < NTAG) {
        rep = g_rep + (long)w * N4;
        wv  = W_aptag + t * HH;
        acc = b_aptag[t];
        off = OUT_AP_OFF + w * NTAG + t;
    } else {
        int tt = t - NTAG;
        rep = g_rep + (long)w * N4 + HH;
        wv  = W_optag + tt * HH;
        acc = b_optag[tt];
        off = OUT_OP_OFF + w * NTAG + tt;
    }
    #pragma unroll 5
    for (int k = 0; k < HH; k++) acc += rep[k] * wv[k];
    out[off] = acc;
}

// ---------------- launch ----------------
extern "C" void kernel_launch(void* const* d_in, const int* in_sizes, int n_in,
                              void* d_out, int out_size) {
    const float* bert      = (const float*)d_in[0];
    const int*   positions = (const int*)  d_in[1];
    const int*   postag    = (const int*)  d_in[2];
    const float* embed     = (const float*)d_in[3];
    const float* W_reduc   = (const float*)d_in[4];
    const float* b_reduc   = (const float*)d_in[5];
    const float* W_ap      = (const float*)d_in[6];
    const float* b_ap      = (const float*)d_in[7];
    const float* W_op      = (const float*)d_in[8];
    const float* b_op      = (const float*)d_in[9];
    const float* W_ap2     = (const float*)d_in[10];
    const float* b_ap2     = (const float*)d_in[11];
    const float* W_op2     = (const float*)d_in[12];
    const float* b_op2     = (const float*)d_in[13];
    const float* W_aptag   = (const float*)d_in[14];
    const float* b_aptag   = (const float*)d_in[15];
    const float* W_optag   = (const float*)d_in[16];
    const float* b_optag   = (const float*)d_in[17];
    const float* W_bi      = (const float*)d_in[18];
    float* out = (float*)d_out;

    void* p;
    cudaGetSymbolAddress(&p, g_hh);   bf16* phh  = (bf16*)p;
    cudaGetSymbolAddress(&p, g_hl);   bf16* phl  = (bf16*)p;
    cudaGetSymbolAddress(&p, g_rdh);  bf16* prdh = (bf16*)p;
    cudaGetSymbolAddress(&p, g_rdl);  bf16* prdl = (bf16*)p;
    cudaGetSymbolAddress(&p, g_i1h);  bf16* pi1h = (bf16*)p;
    cudaGetSymbolAddress(&p, g_i1l);  bf16* pi1l = (bf16*)p;
    cudaGetSymbolAddress(&p, g_onh);  bf16* ponh = (bf16*)p;
    cudaGetSymbolAddress(&p, g_onl);  bf16* ponl = (bf16*)p;
    cudaGetSymbolAddress(&p, g_afh);  bf16* pafh = (bf16*)p;
    cudaGetSymbolAddress(&p, g_afl);  bf16* pafl = (bf16*)p;
    cudaGetSymbolAddress(&p, g_Wrh);  bf16* pWrh = (bf16*)p;
    cudaGetSymbolAddress(&p, g_Wrl);  bf16* pWrl = (bf16*)p;
    cudaGetSymbolAddress(&p, g_Wch);  bf16* pWch = (bf16*)p;
    cudaGetSymbolAddress(&p, g_Wcl);  bf16* pWcl = (bf16*)p;
    cudaGetSymbolAddress(&p, g_Wbh);  bf16* pWbh = (bf16*)p;
    cudaGetSymbolAddress(&p, g_Wbl);  bf16* pWbl = (bf16*)p;
    cudaGetSymbolAddress(&p, g_bcat); float* pbcat = (float*)p;

    cudaFuncSetAttribute(mma_gemm<0>, cudaFuncAttributeMaxDynamicSharedMemorySize, SMEM_SZ);
    cudaFuncSetAttribute(mma_gemm<1>, cudaFuncAttributeMaxDynamicSharedMemorySize, SMEM_SZ);
    cudaFuncSetAttribute(mma_gemm<2>, cudaFuncAttributeMaxDynamicSharedMemorySize, SMEM_SZ);
    cudaFuncSetAttribute(mma_gemm<3>, cudaFuncAttributeMaxDynamicSharedMemorySize, SMEM_SZ);

    // 1) pack weights + init bias column
    {
        int tot = RR * FP + N4 * KR2 + N4 * KBI2 + N4;
        pack_kernel<<<(tot + 255) / 256, 256>>>(W_ap, b_ap, W_op, b_op, W_ap2, b_ap2,
                                                W_op2, b_op2, W_reduc, W_bi);
        init_kernel<<<(NW + 255) / 256, 256>>>();
    }
    // 2) pool + concat -> bf16 hi/lo
    {
        int tot = NW * FP;
        pool_kernel<<<(tot + 255) / 256, 256>>>(bert, positions, postag, embed);
    }
    // 3) gemm1: reduc = h @ Wr^T + b_reduc   M=25600, N=400, K=832 (26 chunks)
    {
        dim3 grid(7, NW / 128, 1);
        mma_gemm<0><<<grid, 256, SMEM_SZ>>>(phh, phl, FP, 0, pWrh, pWrl, FP, 0,
                                            NW, RR, FP / 32, b_reduc, nullptr);
    }
    // 4) gemm2: rep = relu(reduc @ Wcat^T + bcat)  M=25600, N=600, K=448 (14 chunks)
    {
        dim3 grid(10, NW / 128, 1);
        mma_gemm<1><<<grid, 256, SMEM_SZ>>>(prdh, prdl, KR2, 0, pWch, pWcl, KR2, 0,
                                            NW, N4, KR2 / 32, pbcat, nullptr);
    }
    // 5) tag heads
    {
        int tot = NW * 10;
        tag_kernel<<<(tot + 255) / 256, 256>>>(W_aptag, b_aptag, W_optag, b_optag, out);
    }
    // 6) affine = in1 @ Wbi^T   M=25600, N=600, K=192 (6 chunks)
    {
        dim3 grid(10, NW / 128, 1);
        mma_gemm<2><<<grid, 256, SMEM_SZ>>>(pi1h, pi1l, KBI2, 0, pWbh, pWbl, KBI2, 0,
                                            NW, N4, KBI2 / 32, nullptr, nullptr);
    }
    // 7) tri: batched  M=200, N=800, K=192 per batch (6 chunks)
    {
        dim3 grid(13, 2, BB);
        mma_gemm<3><<<grid, 256, SMEM_SZ>>>(ponh, ponl, KBI2, (long)LL * KBI2,
                                            pafh, pafl, KBI2, (long)LL * 4 * KBI2,
                                            LL, KTRI, KBI2 / 32, nullptr, out);
    }
}

// round 10
// speedup vs baseline: 1.7429x; 1.0151x over previous
#include <cuda_runtime.h>
#include <cuda_bf16.h>
#include <cstdint>

// ---------------- problem constants ----------------
#define BB   128
#define SS   256
#define LL   200
#define DD   768
#define PD   50
#define FF   818
#define FP   832             // gemm1 K (padded)
#define RR   400
#define KR2  448             // gemm2 K padded
#define HH   150
#define NW   (BB * LL)       // 25600
#define NTAG 5
#define N4   600
#define KBI2 192             // affine/tri K padded (151 -> 192)
#define KTRI 800
#define OUT_AP_OFF  0
#define OUT_OP_OFF  (NW * NTAG)
#define OUT_TRI_OFF (2 * NW * NTAG)

typedef __nv_bfloat16 bf16;

// ---------------- scratch (__device__ globals, zero-init) ----------------
__device__ bf16  g_hh[NW * FP],  g_hl[NW * FP];
__device__ bf16  g_rdh[NW * KR2], g_rdl[NW * KR2];
__device__ float g_rep[NW * N4];
__device__ bf16  g_i1h[NW * KBI2], g_i1l[NW * KBI2];
__device__ bf16  g_onh[NW * KBI2], g_onl[NW * KBI2];
__device__ bf16  g_afh[NW * 4 * KBI2], g_afl[NW * 4 * KBI2];
__device__ bf16  g_Wrh[RR * FP],  g_Wrl[RR * FP];
__device__ bf16  g_Wch[N4 * KR2], g_Wcl[N4 * KR2];
__device__ bf16  g_Wbh[N4 * KBI2], g_Wbl[N4 * KBI2];
__device__ float g_bcat[N4];

__device__ __forceinline__ void bsplit(float v, bf16* ph, bf16* pl) {
    bf16 h = __float2bfloat16(v);
    *ph = h;
    *pl = __float2bfloat16(v - __bfloat162float(h));
}

// ---------------- PTX helpers (baseline sm_80+ features only) ----------------
__device__ __forceinline__ uint32_t sm_u32(const void* p) {
    uint32_t a;
    asm("{ .reg .u64 t; cvta.to.shared.u64 t, %1; cvt.u32.u64 %0, t; }" : "=r"(a) : "l"(p));
    return a;
}

#define CP16(dst, src) \
    asm volatile("cp.async.cg.shared.global [%0], [%1], 16;" :: "r"(dst), "l"(src) : "memory")
#define CP_COMMIT() asm volatile("cp.async.commit_group;" ::: "memory")
#define CP_WAIT1()  asm volatile("cp.async.wait_group 1;" ::: "memory")
#define CP_WAIT0()  asm volatile("cp.async.wait_group 0;" ::: "memory")

#define LDSM4(r0, r1, r2, r3, addr) \
    asm volatile("ldmatrix.sync.aligned.m8n8.x4.shared.b16 {%0,%1,%2,%3}, [%4];" \
                 : "=r"(r0), "=r"(r1), "=r"(r2), "=r"(r3) : "r"(addr))

#define MMA16816(d, a0, a1, a2, a3, b0, b1) \
    asm volatile("mma.sync.aligned.m16n8k16.row.col.f32.bf16.bf16.f32 " \
                 "{%0,%1,%2,%3}, {%4,%5,%6,%7}, {%8,%9}, {%0,%1,%2,%3};" \
                 : "+f"((d)[0]), "+f"((d)[1]), "+f"((d)[2]), "+f"((d)[3]) \
                 : "r"(a0), "r"(a1), "r"(a2), "r"(a3), "r"(b0), "r"(b1))

// smem stage layout (bytes): A 128x32 bf16 (row stride 40 bf16 = 80B), B 64x32 bf16
#define S_AH    0
#define S_AL    10240
#define S_BH    20480
#define S_BL    25600
#define S_STAGE 30720
#define NSTAGE  3
#define SMEM_SZ (NSTAGE * S_STAGE)    // 92160

// ---------------- HMMA GEMM: C[M,N] = (Ahi+Alo)[M,K] * (Bhi+Blo)[N,K]^T ----
// 128x64 block tile, 8 warps (4Mx2N), warp tile 32x32, BK=32.
// 3-stage cp.async pipeline, ONE __syncthreads per chunk.
// MODE 0: +bias -> reduc hi/lo;  MODE 1: relu(+bias) -> g_rep + in1/opn splits;
// MODE 2: -> aff hi/lo;          MODE 3: batched (z) -> out triplet.
template<int MODE>
__global__ __launch_bounds__(256, 2) void mma_gemm(
    const bf16* __restrict__ Ahi, const bf16* __restrict__ Alo, int lda, long aStride,
    const bf16* __restrict__ Bhi, const bf16* __restrict__ Blo, int ldb, long bStride,
    int M, int N, int nchunk,
    const float* __restrict__ bias, float* __restrict__ out)
{
    extern __shared__ char smem[];
    const uint32_t sbase = sm_u32(smem);
    const int tid = threadIdx.x;
    const int lane = tid & 31;
    const int warp = tid >> 5;
    const int warpM = warp >> 1;       // 0..3
    const int warpN = warp & 1;        // 0..1
    const int rowBase = blockIdx.y * 128;
    const int colBase = blockIdx.x * 64;
    const int z = blockIdx.z;

    const bf16* ahi = Ahi + (long)z * aStride;
    const bf16* alo = Alo + (long)z * aStride;
    const bf16* bhi = Bhi + (long)z * bStride;
    const bf16* blo = Blo + (long)z * bStride;

    // loader mapping
    const int lrow = tid >> 2;         // 0..63
    const int lc8  = tid & 3;          // 16B chunk within 64B row-chunk

    // ldmatrix per-lane offsets
    const int a_row = (lane & 7) + ((lane >> 3) & 1) * 8;
    const int a_kh  = lane >> 4;
    const uint32_t aoff = (uint32_t)((warpM * 32 + a_row) * 80 + a_kh * 16);
    const int b_n  = (lane & 7) + (lane >> 4) * 8;
    const int b_kh = (lane >> 3) & 1;
    const uint32_t boff = (uint32_t)((warpN * 32 + b_n) * 80 + b_kh * 16);

    float acc[2][4][4];
    #pragma unroll
    for (int m = 0; m < 2; m++)
        #pragma unroll
        for (int t = 0; t < 4; t++)
            #pragma unroll
            for (int r = 0; r < 4; r++) acc[m][t][r] = 0.f;

    // ---- async copy of one K-chunk (32 bf16) into stage buffer ----
    auto issue = [&](int c) {
        const uint32_t bufb = sbase + (c % NSTAGE) * S_STAGE;
        const int kof = c * 32 + lc8 * 8;
        #pragma unroll
        for (int t = 0; t < 2; t++) {
            int row = lrow + t * 64;
            long gr = rowBase + row; if (gr > M - 1) gr = M - 1;
            uint32_t d = bufb + row * 80 + lc8 * 16;
            CP16(d + S_AH, ahi + gr * (long)lda + kof);
            CP16(d + S_AL, alo + gr * (long)lda + kof);
        }
        {
            long gn = colBase + lrow; if (gn > N - 1) gn = N - 1;
            uint32_t d = bufb + lrow * 80 + lc8 * 16;
            CP16(d + S_BH, bhi + gn * (long)ldb + kof);
            CP16(d + S_BL, blo + gn * (long)ldb + kof);
        }
        CP_COMMIT();
    };

    issue(0);
    if (nchunk > 1) issue(1);

    for (int c = 0; c < nchunk; c++) {
        // ensure group c landed
        if (c + 1 < nchunk) CP_WAIT1(); else CP_WAIT0();
        __syncthreads();
        // prefetch chunk c+2 into the buffer drained at iter c-1 (safe after sync)
        if (c + 2 < nchunk) issue(c + 2);

        const uint32_t bb = sbase + (c % NSTAGE) * S_STAGE;
        #pragma unroll
        for (int k16 = 0; k16 < 2; k16++) {
            const uint32_t ka = bb + k16 * 32 + aoff;
            const uint32_t kb = bb + k16 * 32 + boff;
            uint32_t ah[8], al[8], bh[8], bl[8];
            LDSM4(ah[0], ah[1], ah[2], ah[3], ka + S_AH);
            LDSM4(ah[4], ah[5], ah[6], ah[7], ka + S_AH + 16 * 80);
            LDSM4(al[0], al[1], al[2], al[3], ka + S_AL);
            LDSM4(al[4], al[5], al[6], al[7], ka + S_AL + 16 * 80);
            LDSM4(bh[0], bh[1], bh[2], bh[3], kb + S_BH);
            LDSM4(bh[4], bh[5], bh[6], bh[7], kb + S_BH + 16 * 80);
            LDSM4(bl[0], bl[1], bl[2], bl[3], kb + S_BL);
            LDSM4(bl[4], bl[5], bl[6], bl[7], kb + S_BL + 16 * 80);
            #pragma unroll
            for (int m = 0; m < 2; m++) {
                #pragma unroll
                for (int t8 = 0; t8 < 4; t8++) {
                    int g = t8 >> 1, s = t8 & 1;
                    uint32_t bh0 = bh[g * 4 + s * 2], bh1 = bh[g * 4 + s * 2 + 1];
                    uint32_t bl0 = bl[g * 4 + s * 2], bl1 = bl[g * 4 + s * 2 + 1];
                    MMA16816(acc[m][t8], ah[m*4], ah[m*4+1], ah[m*4+2], ah[m*4+3], bh0, bh1);
                    MMA16816(acc[m][t8], ah[m*4], ah[m*4+1], ah[m*4+2], ah[m*4+3], bl0, bl1);
                    MMA16816(acc[m][t8], al[m*4], al[m*4+1], al[m*4+2], al[m*4+3], bh0, bh1);
                }
            }
        }
    }

    // ---- epilogue ----
    const int lr = lane >> 2;
    const int lc = (lane & 3) * 2;
    #pragma unroll
    for (int m = 0; m < 2; m++) {
        #pragma unroll
        for (int t8 = 0; t8 < 4; t8++) {
            #pragma unroll
            for (int ri = 0; ri < 4; ri++) {
                int gm = rowBase + warpM * 32 + m * 16 + lr + ((ri & 2) ? 8 : 0);
                int gn = colBase + warpN * 32 + t8 * 8 + lc + (ri & 1);
                if (gm >= M || gn >= N) continue;
                float v = acc[m][t8][ri];
                if (MODE == 0) {
                    v += bias[gn];
                    bsplit(v, &g_rdh[(long)gm * KR2 + gn], &g_rdl[(long)gm * KR2 + gn]);
                } else if (MODE == 1) {
                    v = fmaxf(v + bias[gn], 0.f);
                    g_rep[(long)gm * N4 + gn] = v;
                    if (gn >= 300 && gn < 450)
                        bsplit(v, &g_i1h[(long)gm * KBI2 + gn - 300],
                                  &g_i1l[(long)gm * KBI2 + gn - 300]);
                    else if (gn >= 450)
                        bsplit(v, &g_onh[(long)gm * KBI2 + gn - 450],
                                  &g_onl[(long)gm * KBI2 + gn - 450]);
                } else if (MODE == 2) {
                    int p = gn / HH, h = gn - p * HH;
                    long o = ((long)gm * 4 + p) * KBI2 + h;
                    bsplit(v, &g_afh[o], &g_afl[o]);
                } else {
                    out[(long)OUT_TRI_OFF + ((long)z * LL + gm) * KTRI + gn] = v;
                }
            }
        }
    }
}

// ---------------- pack weights into bf16 hi/lo (padded K) ----------------
__global__ void pack_kernel(const float* __restrict__ W_ap, const float* __restrict__ b_ap,
                            const float* __restrict__ W_op, const float* __restrict__ b_op,
                            const float* __restrict__ W_ap2, const float* __restrict__ b_ap2,
                            const float* __restrict__ W_op2, const float* __restrict__ b_op2,
                            const float* __restrict__ W_reduc, const float* __restrict__ W_bi) {
    int idx = blockIdx.x * blockDim.x + threadIdx.x;
    const int T0 = RR * FP;
    const int T1 = T0 + N4 * KR2;
    const int T2 = T1 + N4 * KBI2;
    const int T3 = T2 + N4;
    if (idx < T0) {
        int n = idx / FP, k = idx - n * FP;
        float v = (k < FF) ? W_reduc[n * FF + k] : 0.f;
        bsplit(v, &g_Wrh[idx], &g_Wrl[idx]);
    } else if (idx < T1) {
        int i = idx - T0;
        int n = i / KR2, k = i - n * KR2;
        float v = 0.f;
        if (k < RR) {
            const float* src; int nn = n;
            if (n < HH)          { src = W_ap;  }
            else if (n < 2 * HH) { src = W_op;  nn = n - HH; }
            else if (n < 3 * HH) { src = W_ap2; nn = n - 2 * HH; }
            else                 { src = W_op2; nn = n - 3 * HH; }
            v = src[nn * RR + k];
        }
        bsplit(v, &g_Wch[i], &g_Wcl[i]);
    } else if (idx < T2) {
        int i = idx - T1;
        int n = i / KBI2, k = i - n * KBI2;
        float v = (k < HH + 1) ? W_bi[n * (HH + 1) + k] : 0.f;
        bsplit(v, &g_Wbh[i], &g_Wbl[i]);
    } else if (idx < T3) {
        int n = idx - T2;
        const float* src; int nn = n;
        if (n < HH)          { src = b_ap;  }
        else if (n < 2 * HH) { src = b_op;  nn = n - HH; }
        else if (n < 3 * HH) { src = b_ap2; nn = n - 2 * HH; }
        else                 { src = b_op2; nn = n - 3 * HH; }
        g_bcat[n] = src[nn];
    }
}

// set bias-1 column of in1
__global__ void init_kernel() {
    int w = blockIdx.x * blockDim.x + threadIdx.x;
    if (w < NW) {
        g_i1h[(long)w * KBI2 + HH] = __float2bfloat16(1.0f);
        g_i1l[(long)w * KBI2 + HH] = __float2bfloat16(0.0f);
    }
}

// ---------------- pool subwords + concat pos embedding -> bf16 hi/lo ----------------
__global__ void pool_kernel(const float* __restrict__ bert,
                            const int* __restrict__ positions,
                            const int* __restrict__ postag,
                            const float* __restrict__ embed) {
    int idx = blockIdx.x * blockDim.x + threadIdx.x;
    if (idx >= NW * FP) return;
    int w = idx / FP;
    int f = idx - w * FP;
    float v = 0.f;
    if (f < PD) {
        v = embed[postag[w] * PD + f];
    } else if (f < FF) {
        int d  = f - PD;
        int s0 = positions[2 * w];
        int s1 = positions[2 * w + 1];
        int b  = w / LL;
        const float* base = bert + ((long)b * SS) * DD + d;
        float s = 0.f;
        for (int t = s0; t <= s1; t++) s += base[(long)t * DD];
        v = s / (float)(s1 - s0 + 1);
    }
    bsplit(v, &g_hh[idx], &g_hl[idx]);
}

// ---------------- tag heads (tiny) ----------------
__global__ void tag_kernel(const float* __restrict__ W_aptag, const float* __restrict__ b_aptag,
                           const float* __restrict__ W_optag, const float* __restrict__ b_optag,
                           float* __restrict__ out) {
    int idx = blockIdx.x * blockDim.x + threadIdx.x;
    if (idx >= NW * 10) return;
    int w = idx / 10, t = idx - w * 10;
    const float* rep;
    const float* wv;
    float acc;
    int off;
    if (t < NTAG) {
        rep = g_rep + (long)w * N4;
        wv  = W_aptag + t * HH;
        acc = b_aptag[t];
        off = OUT_AP_OFF + w * NTAG + t;
    } else {
        int tt = t - NTAG;
        rep = g_rep + (long)w * N4 + HH;
        wv  = W_optag + tt * HH;
        acc = b_optag[tt];
        off = OUT_OP_OFF + w * NTAG + tt;
    }
    #pragma unroll 5
    for (int k = 0; k < HH; k++) acc += rep[k] * wv[k];
    out[off] = acc;
}

// ---------------- launch ----------------
extern "C" void kernel_launch(void* const* d_in, const int* in_sizes, int n_in,
                              void* d_out, int out_size) {
    const float* bert      = (const float*)d_in[0];
    const int*   positions = (const int*)  d_in[1];
    const int*   postag    = (const int*)  d_in[2];
    const float* embed     = (const float*)d_in[3];
    const float* W_reduc   = (const float*)d_in[4];
    const float* b_reduc   = (const float*)d_in[5];
    const float* W_ap      = (const float*)d_in[6];
    const float* b_ap      = (const float*)d_in[7];
    const float* W_op      = (const float*)d_in[8];
    const float* b_op      = (const float*)d_in[9];
    const float* W_ap2     = (const float*)d_in[10];
    const float* b_ap2     = (const float*)d_in[11];
    const float* W_op2     = (const float*)d_in[12];
    const float* b_op2     = (const float*)d_in[13];
    const float* W_aptag   = (const float*)d_in[14];
    const float* b_aptag   = (const float*)d_in[15];
    const float* W_optag   = (const float*)d_in[16];
    const float* b_optag   = (const float*)d_in[17];
    const float* W_bi      = (const float*)d_in[18];
    float* out = (float*)d_out;

    void* p;
    cudaGetSymbolAddress(&p, g_hh);   bf16* phh  = (bf16*)p;
    cudaGetSymbolAddress(&p, g_hl);   bf16* phl  = (bf16*)p;
    cudaGetSymbolAddress(&p, g_rdh);  bf16* prdh = (bf16*)p;
    cudaGetSymbolAddress(&p, g_rdl);  bf16* prdl = (bf16*)p;
    cudaGetSymbolAddress(&p, g_i1h);  bf16* pi1h = (bf16*)p;
    cudaGetSymbolAddress(&p, g_i1l);  bf16* pi1l = (bf16*)p;
    cudaGetSymbolAddress(&p, g_onh);  bf16* ponh = (bf16*)p;
    cudaGetSymbolAddress(&p, g_onl);  bf16* ponl = (bf16*)p;
    cudaGetSymbolAddress(&p, g_afh);  bf16* pafh = (bf16*)p;
    cudaGetSymbolAddress(&p, g_afl);  bf16* pafl = (bf16*)p;
    cudaGetSymbolAddress(&p, g_Wrh);  bf16* pWrh = (bf16*)p;
    cudaGetSymbolAddress(&p, g_Wrl);  bf16* pWrl = (bf16*)p;
    cudaGetSymbolAddress(&p, g_Wch);  bf16* pWch = (bf16*)p;
    cudaGetSymbolAddress(&p, g_Wcl);  bf16* pWcl = (bf16*)p;
    cudaGetSymbolAddress(&p, g_Wbh);  bf16* pWbh = (bf16*)p;
    cudaGetSymbolAddress(&p, g_Wbl);  bf16* pWbl = (bf16*)p;
    cudaGetSymbolAddress(&p, g_bcat); float* pbcat = (float*)p;

    cudaFuncSetAttribute(mma_gemm<0>, cudaFuncAttributeMaxDynamicSharedMemorySize, SMEM_SZ);
    cudaFuncSetAttribute(mma_gemm<1>, cudaFuncAttributeMaxDynamicSharedMemorySize, SMEM_SZ);
    cudaFuncSetAttribute(mma_gemm<2>, cudaFuncAttributeMaxDynamicSharedMemorySize, SMEM_SZ);
    cudaFuncSetAttribute(mma_gemm<3>, cudaFuncAttributeMaxDynamicSharedMemorySize, SMEM_SZ);

    // 1) pack weights + init bias column
    {
        int tot = RR * FP + N4 * KR2 + N4 * KBI2 + N4;
        pack_kernel<<<(tot + 255) / 256, 256>>>(W_ap, b_ap, W_op, b_op, W_ap2, b_ap2,
                                                W_op2, b_op2, W_reduc, W_bi);
        init_kernel<<<(NW + 255) / 256, 256>>>();
    }
    // 2) pool + concat -> bf16 hi/lo
    {
        int tot = NW * FP;
        pool_kernel<<<(tot + 255) / 256, 256>>>(bert, positions, postag, embed);
    }
    // 3) gemm1: reduc = h @ Wr^T + b_reduc   M=25600, N=400, K=832 (26 chunks)
    {
        dim3 grid(7, NW / 128, 1);
        mma_gemm<0><<<grid, 256, SMEM_SZ>>>(phh, phl, FP, 0, pWrh, pWrl, FP, 0,
                                            NW, RR, FP / 32, b_reduc, nullptr);
    }
    // 4) gemm2: rep = relu(reduc @ Wcat^T + bcat)  M=25600, N=600, K=448 (14 chunks)
    {
        dim3 grid(10, NW / 128, 1);
        mma_gemm<1><<<grid, 256, SMEM_SZ>>>(prdh, prdl, KR2, 0, pWch, pWcl, KR2, 0,
                                            NW, N4, KR2 / 32, pbcat, nullptr);
    }
    // 5) tag heads
    {
        int tot = NW * 10;
        tag_kernel<<<(tot + 255) / 256, 256>>>(W_aptag, b_aptag, W_optag, b_optag, out);
    }
    // 6) affine = in1 @ Wbi^T   M=25600, N=600, K=192 (6 chunks)
    {
        dim3 grid(10, NW / 128, 1);
        mma_gemm<2><<<grid, 256, SMEM_SZ>>>(pi1h, pi1l, KBI2, 0, pWbh, pWbl, KBI2, 0,
                                            NW, N4, KBI2 / 32, nullptr, nullptr);
    }
    // 7) tri: batched  M=200, N=800, K=192 per batch (6 chunks)
    {
        dim3 grid(13, 2, BB);
        mma_gemm<3><<<grid, 256, SMEM_SZ>>>(ponh, ponl, KBI2, (long)LL * KBI2,
                                            pafh, pafl, KBI2, (long)LL * 4 * KBI2,
                                            LL, KTRI, KBI2 / 32, nullptr, out);
    }
}

// round 11
// speedup vs baseline: 1.8631x; 1.0690x over previous
#include <cuda_runtime.h>
#include <cuda_bf16.h>
#include <cstdint>

// ---------------- problem constants ----------------
#define BB   128
#define SS   256
#define LL   200
#define DD   768
#define PD   50
#define FF   818
#define FP   832             // gemm1 K (padded)
#define RR   400
#define KR2  416             // gemm2 K padded (400 -> 416)
#define HH   150
#define NW   (BB * LL)       // 25600
#define NTAG 5
#define N4   600
#define KBI2 192             // affine/tri K padded (151 -> 192)
#define KTRI 800
#define OUT_AP_OFF  0
#define OUT_OP_OFF  (NW * NTAG)
#define OUT_TRI_OFF (2 * NW * NTAG)

typedef __nv_bfloat16 bf16;

// ---------------- scratch (__device__ globals, zero-init) ----------------
__device__ bf16  g_hh[NW * FP],  g_hl[NW * FP];
__device__ bf16  g_rdh[NW * KR2], g_rdl[NW * KR2];
__device__ float g_rep[NW * N4];
__device__ bf16  g_i1h[NW * KBI2], g_i1l[NW * KBI2];
__device__ bf16  g_onh[NW * KBI2], g_onl[NW * KBI2];
__device__ bf16  g_afh[NW * 4 * KBI2], g_afl[NW * 4 * KBI2];
__device__ bf16  g_Wrh[RR * FP],  g_Wrl[RR * FP];
__device__ bf16  g_Wch[N4 * KR2], g_Wcl[N4 * KR2];
__device__ bf16  g_Wbh[N4 * KBI2], g_Wbl[N4 * KBI2];
__device__ float g_bcat[N4];

__device__ __forceinline__ void bsplit(float v, bf16* ph, bf16* pl) {
    bf16 h = __float2bfloat16(v);
    *ph = h;
    *pl = __float2bfloat16(v - __bfloat162float(h));
}

// ---------------- PTX helpers (baseline sm_80+ features only) ----------------
__device__ __forceinline__ uint32_t sm_u32(const void* p) {
    uint32_t a;
    asm("{ .reg .u64 t; cvta.to.shared.u64 t, %1; cvt.u32.u64 %0, t; }" : "=r"(a) : "l"(p));
    return a;
}

#define CP16(dst, src) \
    asm volatile("cp.async.cg.shared.global [%0], [%1], 16;" :: "r"(dst), "l"(src) : "memory")
#define CP_COMMIT() asm volatile("cp.async.commit_group;" ::: "memory")
#define CP_WAIT0()  asm volatile("cp.async.wait_group 0;" ::: "memory")

#define LDSM4(r0, r1, r2, r3, addr) \
    asm volatile("ldmatrix.sync.aligned.m8n8.x4.shared.b16 {%0,%1,%2,%3}, [%4];" \
                 : "=r"(r0), "=r"(r1), "=r"(r2), "=r"(r3) : "r"(addr))

#define MMA16816(d, a0, a1, a2, a3, b0, b1) \
    asm volatile("mma.sync.aligned.m16n8k16.row.col.f32.bf16.bf16.f32 " \
                 "{%0,%1,%2,%3}, {%4,%5,%6,%7}, {%8,%9}, {%0,%1,%2,%3};" \
                 : "+f"((d)[0]), "+f"((d)[1]), "+f"((d)[2]), "+f"((d)[3]) \
                 : "r"(a0), "r"(a1), "r"(a2), "r"(a3), "r"(b0), "r"(b1))

// smem stage layout (bytes): A 128x32 bf16 (row stride 40 bf16 = 80B), B 64x32 bf16
#define S_AH    0
#define S_AL    10240
#define S_BH    20480
#define S_BL    25600
#define S_STAGE 30720
#define NSTAGE  2
#define SMEM_SZ (NSTAGE * S_STAGE)    // 61440  -> 3 CTAs/SM

// ---------------- HMMA GEMM: C[M,N] = (Ahi+Alo)[M,K] * (Bhi+Blo)[N,K]^T ----
// 128x64 block tile, 8 warps (4Mx2N), warp tile 32x32, BK=32.
// 2-stage cp.async pipeline, ONE __syncthreads per chunk, 3 CTAs/SM.
// Schedule per chunk c:  wait0(copy c done) -> sync -> issue(c+1) -> compute(c).
// The sync guarantees every warp finished compute(c-1), so writing buffer
// (c+1)&1 (last read in c-1) after the sync is hazard-free.
// MODE 0: +bias -> reduc hi/lo;  MODE 1: relu(+bias) -> g_rep + in1/opn splits;
// MODE 2: -> aff hi/lo;          MODE 3: batched (z) -> out triplet.
template<int MODE>
__global__ __launch_bounds__(256, 3) void mma_gemm(
    const bf16* __restrict__ Ahi, const bf16* __restrict__ Alo, int lda, long aStride,
    const bf16* __restrict__ Bhi, const bf16* __restrict__ Blo, int ldb, long bStride,
    int M, int N, int nchunk,
    const float* __restrict__ bias, float* __restrict__ out)
{
    extern __shared__ char smem[];
    const uint32_t sbase = sm_u32(smem);
    const int tid = threadIdx.x;
    const int lane = tid & 31;
    const int warp = tid >> 5;
    const int warpM = warp >> 1;       // 0..3
    const int warpN = warp & 1;        // 0..1
    const int rowBase = blockIdx.y * 128;
    const int colBase = blockIdx.x * 64;
    const int z = blockIdx.z;

    const bf16* ahi = Ahi + (long)z * aStride;
    const bf16* alo = Alo + (long)z * aStride;
    const bf16* bhi = Bhi + (long)z * bStride;
    const bf16* blo = Blo + (long)z * bStride;

    // loader mapping
    const int lrow = tid >> 2;         // 0..63
    const int lc8  = tid & 3;          // 16B chunk within 64B row-chunk

    // ldmatrix per-lane offsets
    const int a_row = (lane & 7) + ((lane >> 3) & 1) * 8;
    const int a_kh  = lane >> 4;
    const uint32_t aoff = (uint32_t)((warpM * 32 + a_row) * 80 + a_kh * 16);
    const int b_n  = (lane & 7) + (lane >> 4) * 8;
    const int b_kh = (lane >> 3) & 1;
    const uint32_t boff = (uint32_t)((warpN * 32 + b_n) * 80 + b_kh * 16);

    float acc[2][4][4];
    #pragma unroll
    for (int m = 0; m < 2; m++)
        #pragma unroll
        for (int t = 0; t < 4; t++)
            #pragma unroll
            for (int r = 0; r < 4; r++) acc[m][t][r] = 0.f;

    // ---- async copy of one K-chunk (32 bf16) into stage buffer ----
    auto issue = [&](int c) {
        const uint32_t bufb = sbase + (c & 1) * S_STAGE;
        const int kof = c * 32 + lc8 * 8;
        #pragma unroll
        for (int t = 0; t < 2; t++) {
            int row = lrow + t * 64;
            long gr = rowBase + row; if (gr > M - 1) gr = M - 1;
            uint32_t d = bufb + row * 80 + lc8 * 16;
            CP16(d + S_AH, ahi + gr * (long)lda + kof);
            CP16(d + S_AL, alo + gr * (long)lda + kof);
        }
        {
            long gn = colBase + lrow; if (gn > N - 1) gn = N - 1;
            uint32_t d = bufb + lrow * 80 + lc8 * 16;
            CP16(d + S_BH, bhi + gn * (long)ldb + kof);
            CP16(d + S_BL, blo + gn * (long)ldb + kof);
        }
        CP_COMMIT();
    };

    issue(0);
    for (int c = 0; c < nchunk; c++) {
        CP_WAIT0();                 // copy of chunk c landed
        __syncthreads();            // everyone done computing chunk c-1
        if (c + 1 < nchunk) issue(c + 1);   // overlaps compute(c)

        const uint32_t bb = sbase + (c & 1) * S_STAGE;
        #pragma unroll
        for (int k16 = 0; k16 < 2; k16++) {
            const uint32_t ka = bb + k16 * 32 + aoff;
            const uint32_t kb = bb + k16 * 32 + boff;
            uint32_t ah[8], al[8], bh[8], bl[8];
            LDSM4(ah[0], ah[1], ah[2], ah[3], ka + S_AH);
            LDSM4(ah[4], ah[5], ah[6], ah[7], ka + S_AH + 16 * 80);
            LDSM4(al[0], al[1], al[2], al[3], ka + S_AL);
            LDSM4(al[4], al[5], al[6], al[7], ka + S_AL + 16 * 80);
            LDSM4(bh[0], bh[1], bh[2], bh[3], kb + S_BH);
            LDSM4(bh[4], bh[5], bh[6], bh[7], kb + S_BH + 16 * 80);
            LDSM4(bl[0], bl[1], bl[2], bl[3], kb + S_BL);
            LDSM4(bl[4], bl[5], bl[6], bl[7], kb + S_BL + 16 * 80);
            #pragma unroll
            for (int m = 0; m < 2; m++) {
                #pragma unroll
                for (int t8 = 0; t8 < 4; t8++) {
                    int g = t8 >> 1, s = t8 & 1;
                    uint32_t bh0 = bh[g * 4 + s * 2], bh1 = bh[g * 4 + s * 2 + 1];
                    uint32_t bl0 = bl[g * 4 + s * 2], bl1 = bl[g * 4 + s * 2 + 1];
                    MMA16816(acc[m][t8], ah[m*4], ah[m*4+1], ah[m*4+2], ah[m*4+3], bh0, bh1);
                    MMA16816(acc[m][t8], ah[m*4], ah[m*4+1], ah[m*4+2], ah[m*4+3], bl0, bl1);
                    MMA16816(acc[m][t8], al[m*4], al[m*4+1], al[m*4+2], al[m*4+3], bh0, bh1);
                }
            }
        }
    }

    // ---- epilogue ----
    const int lr = lane >> 2;
    const int lc = (lane & 3) * 2;
    #pragma unroll
    for (int m = 0; m < 2; m++) {
        #pragma unroll
        for (int t8 = 0; t8 < 4; t8++) {
            #pragma unroll
            for (int ri = 0; ri < 4; ri++) {
                int gm = rowBase + warpM * 32 + m * 16 + lr + ((ri & 2) ? 8 : 0);
                int gn = colBase + warpN * 32 + t8 * 8 + lc + (ri & 1);
                if (gm >= M || gn >= N) continue;
                float v = acc[m][t8][ri];
                if (MODE == 0) {
                    v += bias[gn];
                    bsplit(v, &g_rdh[(long)gm * KR2 + gn], &g_rdl[(long)gm * KR2 + gn]);
                } else if (MODE == 1) {
                    v = fmaxf(v + bias[gn], 0.f);
                    g_rep[(long)gm * N4 + gn] = v;
                    if (gn >= 300 && gn < 450)
                        bsplit(v, &g_i1h[(long)gm * KBI2 + gn - 300],
                                  &g_i1l[(long)gm * KBI2 + gn - 300]);
                    else if (gn >= 450)
                        bsplit(v, &g_onh[(long)gm * KBI2 + gn - 450],
                                  &g_onl[(long)gm * KBI2 + gn - 450]);
                } else if (MODE == 2) {
                    int p = gn / HH, h = gn - p * HH;
                    long o = ((long)gm * 4 + p) * KBI2 + h;
                    bsplit(v, &g_afh[o], &g_afl[o]);
                } else {
                    out[(long)OUT_TRI_OFF + ((long)z * LL + gm) * KTRI + gn] = v;
                }
            }
        }
    }
}

// ---------------- pack weights into bf16 hi/lo (padded K) ----------------
__global__ void pack_kernel(const float* __restrict__ W_ap, const float* __restrict__ b_ap,
                            const float* __restrict__ W_op, const float* __restrict__ b_op,
                            const float* __restrict__ W_ap2, const float* __restrict__ b_ap2,
                            const float* __restrict__ W_op2, const float* __restrict__ b_op2,
                            const float* __restrict__ W_reduc, const float* __restrict__ W_bi) {
    int idx = blockIdx.x * blockDim.x + threadIdx.x;
    const int T0 = RR * FP;
    const int T1 = T0 + N4 * KR2;
    const int T2 = T1 + N4 * KBI2;
    const int T3 = T2 + N4;
    if (idx < T0) {
        int n = idx / FP, k = idx - n * FP;
        float v = (k < FF) ? W_reduc[n * FF + k] : 0.f;
        bsplit(v, &g_Wrh[idx], &g_Wrl[idx]);
    } else if (idx < T1) {
        int i = idx - T0;
        int n = i / KR2, k = i - n * KR2;
        float v = 0.f;
        if (k < RR) {
            const float* src; int nn = n;
            if (n < HH)          { src = W_ap;  }
            else if (n < 2 * HH) { src = W_op;  nn = n - HH; }
            else if (n < 3 * HH) { src = W_ap2; nn = n - 2 * HH; }
            else                 { src = W_op2; nn = n - 3 * HH; }
            v = src[nn * RR + k];
        }
        bsplit(v, &g_Wch[i], &g_Wcl[i]);
    } else if (idx < T2) {
        int i = idx - T1;
        int n = i / KBI2, k = i - n * KBI2;
        float v = (k < HH + 1) ? W_bi[n * (HH + 1) + k] : 0.f;
        bsplit(v, &g_Wbh[i], &g_Wbl[i]);
    } else if (idx < T3) {
        int n = idx - T2;
        const float* src; int nn = n;
        if (n < HH)          { src = b_ap;  }
        else if (n < 2 * HH) { src = b_op;  nn = n - HH; }
        else if (n < 3 * HH) { src = b_ap2; nn = n - 2 * HH; }
        else                 { src = b_op2; nn = n - 3 * HH; }
        g_bcat[n] = src[nn];
    }
}

// set bias-1 column of in1
__global__ void init_kernel() {
    int w = blockIdx.x * blockDim.x + threadIdx.x;
    if (w < NW) {
        g_i1h[(long)w * KBI2 + HH] = __float2bfloat16(1.0f);
        g_i1l[(long)w * KBI2 + HH] = __float2bfloat16(0.0f);
    }
}

// ---------------- pool subwords + concat pos embedding -> bf16 hi/lo ----------------
__global__ void pool_kernel(const float* __restrict__ bert,
                            const int* __restrict__ positions,
                            const int* __restrict__ postag,
                            const float* __restrict__ embed) {
    int idx = blockIdx.x * blockDim.x + threadIdx.x;
    if (idx >= NW * FP) return;
    int w = idx / FP;
    int f = idx - w * FP;
    float v = 0.f;
    if (f < PD) {
        v = embed[postag[w] * PD + f];
    } else if (f < FF) {
        int d  = f - PD;
        int s0 = positions[2 * w];
        int s1 = positions[2 * w + 1];
        int b  = w / LL;
        const float* base = bert + ((long)b * SS) * DD + d;
        float s = 0.f;
        for (int t = s0; t <= s1; t++) s += base[(long)t * DD];
        v = s / (float)(s1 - s0 + 1);
    }
    bsplit(v, &g_hh[idx], &g_hl[idx]);
}

// ---------------- tag heads (tiny) ----------------
__global__ void tag_kernel(const float* __restrict__ W_aptag, const float* __restrict__ b_aptag,
                           const float* __restrict__ W_optag, const float* __restrict__ b_optag,
                           float* __restrict__ out) {
    int idx = blockIdx.x * blockDim.x + threadIdx.x;
    if (idx >= NW * 10) return;
    int w = idx / 10, t = idx - w * 10;
    const float* rep;
    const float* wv;
    float acc;
    int off;
    if (t < NTAG) {
        rep = g_rep + (long)w * N4;
        wv  = W_aptag + t * HH;
        acc = b_aptag[t];
        off = OUT_AP_OFF + w * NTAG + t;
    } else {
        int tt = t - NTAG;
        rep = g_rep + (long)w * N4 + HH;
        wv  = W_optag + tt * HH;
        acc = b_optag[tt];
        off = OUT_OP_OFF + w * NTAG + tt;
    }
    #pragma unroll 5
    for (int k = 0; k < HH; k++) acc += rep[k] * wv[k];
    out[off] = acc;
}

// ---------------- launch ----------------
extern "C" void kernel_launch(void* const* d_in, const int* in_sizes, int n_in,
                              void* d_out, int out_size) {
    const float* bert      = (const float*)d_in[0];
    const int*   positions = (const int*)  d_in[1];
    const int*   postag    = (const int*)  d_in[2];
    const float* embed     = (const float*)d_in[3];
    const float* W_reduc   = (const float*)d_in[4];
    const float* b_reduc   = (const float*)d_in[5];
    const float* W_ap      = (const float*)d_in[6];
    const float* b_ap      = (const float*)d_in[7];
    const float* W_op      = (const float*)d_in[8];
    const float* b_op      = (const float*)d_in[9];
    const float* W_ap2     = (const float*)d_in[10];
    const float* b_ap2     = (const float*)d_in[11];
    const float* W_op2     = (const float*)d_in[12];
    const float* b_op2     = (const float*)d_in[13];
    const float* W_aptag   = (const float*)d_in[14];
    const float* b_aptag   = (const float*)d_in[15];
    const float* W_optag   = (const float*)d_in[16];
    const float* b_optag   = (const float*)d_in[17];
    const float* W_bi      = (const float*)d_in[18];
    float* out = (float*)d_out;

    void* p;
    cudaGetSymbolAddress(&p, g_hh);   bf16* phh  = (bf16*)p;
    cudaGetSymbolAddress(&p, g_hl);   bf16* phl  = (bf16*)p;
    cudaGetSymbolAddress(&p, g_rdh);  bf16* prdh = (bf16*)p;
    cudaGetSymbolAddress(&p, g_rdl);  bf16* prdl = (bf16*)p;
    cudaGetSymbolAddress(&p, g_i1h);  bf16* pi1h = (bf16*)p;
    cudaGetSymbolAddress(&p, g_i1l);  bf16* pi1l = (bf16*)p;
    cudaGetSymbolAddress(&p, g_onh);  bf16* ponh = (bf16*)p;
    cudaGetSymbolAddress(&p, g_onl);  bf16* ponl = (bf16*)p;
    cudaGetSymbolAddress(&p, g_afh);  bf16* pafh = (bf16*)p;
    cudaGetSymbolAddress(&p, g_afl);  bf16* pafl = (bf16*)p;
    cudaGetSymbolAddress(&p, g_Wrh);  bf16* pWrh = (bf16*)p;
    cudaGetSymbolAddress(&p, g_Wrl);  bf16* pWrl = (bf16*)p;
    cudaGetSymbolAddress(&p, g_Wch);  bf16* pWch = (bf16*)p;
    cudaGetSymbolAddress(&p, g_Wcl);  bf16* pWcl = (bf16*)p;
    cudaGetSymbolAddress(&p, g_Wbh);  bf16* pWbh = (bf16*)p;
    cudaGetSymbolAddress(&p, g_Wbl);  bf16* pWbl = (bf16*)p;
    cudaGetSymbolAddress(&p, g_bcat); float* pbcat = (float*)p;

    cudaFuncSetAttribute(mma_gemm<0>, cudaFuncAttributeMaxDynamicSharedMemorySize, SMEM_SZ);
    cudaFuncSetAttribute(mma_gemm<1>, cudaFuncAttributeMaxDynamicSharedMemorySize, SMEM_SZ);
    cudaFuncSetAttribute(mma_gemm<2>, cudaFuncAttributeMaxDynamicSharedMemorySize, SMEM_SZ);
    cudaFuncSetAttribute(mma_gemm<3>, cudaFuncAttributeMaxDynamicSharedMemorySize, SMEM_SZ);

    // 1) pack weights + init bias column
    {
        int tot = RR * FP + N4 * KR2 + N4 * KBI2 + N4;
        pack_kernel<<<(tot + 255) / 256, 256>>>(W_ap, b_ap, W_op, b_op, W_ap2, b_ap2,
                                                W_op2, b_op2, W_reduc, W_bi);
        init_kernel<<<(NW + 255) / 256, 256>>>();
    }
    // 2) pool + concat -> bf16 hi/lo
    {
        int tot = NW * FP;
        pool_kernel<<<(tot + 255) / 256, 256>>>(bert, positions, postag, embed);
    }
    // 3) gemm1: reduc = h @ Wr^T + b_reduc   M=25600, N=400, K=832 (26 chunks)
    {
        dim3 grid(7, NW / 128, 1);
        mma_gemm<0><<<grid, 256, SMEM_SZ>>>(phh, phl, FP, 0, pWrh, pWrl, FP, 0,
                                            NW, RR, FP / 32, b_reduc, nullptr);
    }
    // 4) gemm2: rep = relu(reduc @ Wcat^T + bcat)  M=25600, N=600, K=416 (13 chunks)
    {
        dim3 grid(10, NW / 128, 1);
        mma_gemm<1><<<grid, 256, SMEM_SZ>>>(prdh, prdl, KR2, 0, pWch, pWcl, KR2, 0,
                                            NW, N4, KR2 / 32, pbcat, nullptr);
    }
    // 5) tag heads
    {
        int tot = NW * 10;
        tag_kernel<<<(tot + 255) / 256, 256>>>(W_aptag, b_aptag, W_optag, b_optag, out);
    }
    // 6) affine = in1 @ Wbi^T   M=25600, N=600, K=192 (6 chunks)
    {
        dim3 grid(10, NW / 128, 1);
        mma_gemm<2><<<grid, 256, SMEM_SZ>>>(pi1h, pi1l, KBI2, 0, pWbh, pWbl, KBI2, 0,
                                            NW, N4, KBI2 / 32, nullptr, nullptr);
    }
    // 7) tri: batched  M=200, N=800, K=192 per batch (6 chunks)
    {
        dim3 grid(13, 2, BB);
        mma_gemm<3><<<grid, 256, SMEM_SZ>>>(ponh, ponl, KBI2, (long)LL * KBI2,
                                            pafh, pafl, KBI2, (long)LL * 4 * KBI2,
                                            LL, KTRI, KBI2 / 32, nullptr, out);
    }
}

// round 12
// speedup vs baseline: 2.3356x; 1.2536x over previous
#include <cuda_runtime.h>
#include <cuda_fp16.h>
#include <cstdint>

// ---------------- problem constants ----------------
#define BB   128
#define SS   256
#define LL   200
#define DD   768
#define PD   50
#define FF   818
#define FP   832             // gemm1 K (padded)
#define RR   400
#define KR2  416             // gemm2 K padded
#define HH   150
#define NW   (BB * LL)       // 25600
#define NTAG 5
#define N4   600
#define KBI2 160             // affine/tri K padded (151 -> 160)
#define KTRI 800
#define OUT_AP_OFF  0
#define OUT_OP_OFF  (NW * NTAG)
#define OUT_TRI_OFF (2 * NW * NTAG)

typedef __half f16;

// ---------------- scratch (__device__ globals, zero-init) ----------------
__device__ f16   g_hh[NW * FP],  g_hl[NW * FP];      // pooled features hi/lo (A of gemm1)
__device__ f16   g_rdh[NW * KR2], g_rdl[NW * KR2];   // reduc hi/lo (A of gemm2)
__device__ float g_rep[NW * N4];
__device__ f16   g_i1h[NW * KBI2], g_i1l[NW * KBI2]; // [ap_node,1,0..] (A of affine)
__device__ f16   g_onh[NW * KBI2], g_onl[NW * KBI2]; // [op_node,0..]   (A of tri)
__device__ f16   g_afh[NW * 4 * KBI2];               // affine hi only  (B of tri)
__device__ f16   g_Wrh[RR * FP];                     // B of gemm1 (hi only)
__device__ f16   g_Wch[N4 * KR2];                    // B of gemm2 (hi only)
__device__ f16   g_Wbh[N4 * KBI2];                   // B of affine (hi only)
__device__ float g_bcat[N4];

__device__ __forceinline__ void hsplit(float v, f16* ph, f16* pl) {
    f16 h = __float2half(v);
    *ph = h;
    *pl = __float2half(v - __half2float(h));
}

// ---------------- PTX helpers (baseline sm_80+ features only) ----------------
__device__ __forceinline__ uint32_t sm_u32(const void* p) {
    uint32_t a;
    asm("{ .reg .u64 t; cvta.to.shared.u64 t, %1; cvt.u32.u64 %0, t; }" : "=r"(a) : "l"(p));
    return a;
}

#define CP16(dst, src) \
    asm volatile("cp.async.cg.shared.global [%0], [%1], 16;" :: "r"(dst), "l"(src) : "memory")
#define CP_COMMIT() asm volatile("cp.async.commit_group;" ::: "memory")
#define CP_WAIT0()  asm volatile("cp.async.wait_group 0;" ::: "memory")

#define LDSM4(r0, r1, r2, r3, addr) \
    asm volatile("ldmatrix.sync.aligned.m8n8.x4.shared.b16 {%0,%1,%2,%3}, [%4];" \
                 : "=r"(r0), "=r"(r1), "=r"(r2), "=r"(r3) : "r"(addr))

#define MMA16816(d, a0, a1, a2, a3, b0, b1) \
    asm volatile("mma.sync.aligned.m16n8k16.row.col.f32.f16.f16.f32 " \
                 "{%0,%1,%2,%3}, {%4,%5,%6,%7}, {%8,%9}, {%0,%1,%2,%3};" \
                 : "+f"((d)[0]), "+f"((d)[1]), "+f"((d)[2]), "+f"((d)[3]) \
                 : "r"(a0), "r"(a1), "r"(a2), "r"(a3), "r"(b0), "r"(b1))

// smem stage layout (bytes): rows of 32 f16 = 64B + 16B pad -> 80B row stride
// A_hi 128x32, A_lo 128x32, B_hi 64x32
#define S_AH    0
#define S_AL    10240
#define S_BH    20480
#define S_STAGE 25600
#define NSTAGE  2
#define SMEM_SZ (NSTAGE * S_STAGE)    // 51200 -> 3+ CTAs/SM

// ---------------- HMMA GEMM: C[M,N] = (Ahi+Alo)[M,K] * Bhi[N,K]^T ----
// (B_lo term dropped: fp16 split, rel-err ~2e-4.)
// 128x64 block tile, 8 warps (4Mx2N), warp tile 32x32, BK=32.
// 2-stage cp.async pipeline, one __syncthreads per chunk.
// MODE 0: +bias -> reduc hi/lo;  MODE 1: relu(+bias) -> g_rep + in1/opn splits;
// MODE 2: -> aff hi;             MODE 3: batched (z) -> out triplet.
template<int MODE>
__global__ __launch_bounds__(256, 3) void mma_gemm(
    const f16* __restrict__ Ahi, const f16* __restrict__ Alo, int lda, long aStride,
    const f16* __restrict__ Bhi, int ldb, long bStride,
    int M, int N, int nchunk,
    const float* __restrict__ bias, float* __restrict__ out)
{
    extern __shared__ char smem[];
    const uint32_t sbase = sm_u32(smem);
    const int tid = threadIdx.x;
    const int lane = tid & 31;
    const int warp = tid >> 5;
    const int warpM = warp >> 1;       // 0..3
    const int warpN = warp & 1;        // 0..1
    const int rowBase = blockIdx.y * 128;
    const int colBase = blockIdx.x * 64;
    const int z = blockIdx.z;

    const f16* ahi = Ahi + (long)z * aStride;
    const f16* alo = Alo + (long)z * aStride;
    const f16* bhi = Bhi + (long)z * bStride;

    // loader mapping
    const int lrow = tid >> 2;         // 0..63
    const int lc8  = tid & 3;          // 16B chunk within 64B row

    // ldmatrix per-lane offsets
    const int a_row = (lane & 7) + ((lane >> 3) & 1) * 8;
    const int a_kh  = lane >> 4;
    const uint32_t aoff = (uint32_t)((warpM * 32 + a_row) * 80 + a_kh * 16);
    const int b_n  = (lane & 7) + (lane >> 4) * 8;
    const int b_kh = (lane >> 3) & 1;
    const uint32_t boff = (uint32_t)((warpN * 32 + b_n) * 80 + b_kh * 16);

    float acc[2][4][4];
    #pragma unroll
    for (int m = 0; m < 2; m++)
        #pragma unroll
        for (int t = 0; t < 4; t++)
            #pragma unroll
            for (int r = 0; r < 4; r++) acc[m][t][r] = 0.f;

    // ---- async copy of one K-chunk (32 f16) into stage buffer ----
    auto issue = [&](int c) {
        const uint32_t bufb = sbase + (c & 1) * S_STAGE;
        const int kof = c * 32 + lc8 * 8;
        #pragma unroll
        for (int t = 0; t < 2; t++) {
            int row = lrow + t * 64;
            long gr = rowBase + row; if (gr > M - 1) gr = M - 1;
            uint32_t d = bufb + row * 80 + lc8 * 16;
            CP16(d + S_AH, ahi + gr * (long)lda + kof);
            CP16(d + S_AL, alo + gr * (long)lda + kof);
        }
        {
            long gn = colBase + lrow; if (gn > N - 1) gn = N - 1;
            uint32_t d = bufb + S_BH + lrow * 80 + lc8 * 16;
            CP16(d, bhi + gn * (long)ldb + kof);
        }
        CP_COMMIT();
    };

    issue(0);
    for (int c = 0; c < nchunk; c++) {
        CP_WAIT0();                 // copy of chunk c landed
        __syncthreads();            // everyone done computing chunk c-1
        if (c + 1 < nchunk) issue(c + 1);   // overlaps compute(c)

        const uint32_t bb = sbase + (c & 1) * S_STAGE;
        #pragma unroll
        for (int k16 = 0; k16 < 2; k16++) {
            const uint32_t ka = bb + k16 * 32 + aoff;
            const uint32_t kb = bb + k16 * 32 + boff;
            uint32_t ah[8], al[8], bh[8];
            LDSM4(ah[0], ah[1], ah[2], ah[3], ka + S_AH);
            LDSM4(ah[4], ah[5], ah[6], ah[7], ka + S_AH + 16 * 80);
            LDSM4(al[0], al[1], al[2], al[3], ka + S_AL);
            LDSM4(al[4], al[5], al[6], al[7], ka + S_AL + 16 * 80);
            LDSM4(bh[0], bh[1], bh[2], bh[3], kb + S_BH);
            LDSM4(bh[4], bh[5], bh[6], bh[7], kb + S_BH + 16 * 80);
            #pragma unroll
            for (int m = 0; m < 2; m++) {
                #pragma unroll
                for (int t8 = 0; t8 < 4; t8++) {
                    int g = t8 >> 1, s = t8 & 1;
                    uint32_t b0 = bh[g * 4 + s * 2], b1 = bh[g * 4 + s * 2 + 1];
                    MMA16816(acc[m][t8], ah[m*4], ah[m*4+1], ah[m*4+2], ah[m*4+3], b0, b1);
                    MMA16816(acc[m][t8], al[m*4], al[m*4+1], al[m*4+2], al[m*4+3], b0, b1);
                }
            }
        }
    }

    // ---- epilogue ----
    const int lr = lane >> 2;
    const int lc = (lane & 3) * 2;
    #pragma unroll
    for (int m = 0; m < 2; m++) {
        #pragma unroll
        for (int t8 = 0; t8 < 4; t8++) {
            #pragma unroll
            for (int ri = 0; ri < 4; ri++) {
                int gm = rowBase + warpM * 32 + m * 16 + lr + ((ri & 2) ? 8 : 0);
                int gn = colBase + warpN * 32 + t8 * 8 + lc + (ri & 1);
                if (gm >= M || gn >= N) continue;
                float v = acc[m][t8][ri];
                if (MODE == 0) {
                    v += bias[gn];
                    hsplit(v, &g_rdh[(long)gm * KR2 + gn], &g_rdl[(long)gm * KR2 + gn]);
                } else if (MODE == 1) {
                    v = fmaxf(v + bias[gn], 0.f);
                    g_rep[(long)gm * N4 + gn] = v;
                    if (gn >= 300 && gn < 450)
                        hsplit(v, &g_i1h[(long)gm * KBI2 + gn - 300],
                                  &g_i1l[(long)gm * KBI2 + gn - 300]);
                    else if (gn >= 450)
                        hsplit(v, &g_onh[(long)gm * KBI2 + gn - 450],
                                  &g_onl[(long)gm * KBI2 + gn - 450]);
                } else if (MODE == 2) {
                    int p = gn / HH, h = gn - p * HH;
                    g_afh[((long)gm * 4 + p) * KBI2 + h] = __float2half(v);
                } else {
                    out[(long)OUT_TRI_OFF + ((long)z * LL + gm) * KTRI + gn] = v;
                }
            }
        }
    }
}

// ---------------- pack weights into f16 hi (B-side needs hi only) ----------------
__global__ void pack_kernel(const float* __restrict__ W_ap, const float* __restrict__ b_ap,
                            const float* __restrict__ W_op, const float* __restrict__ b_op,
                            const float* __restrict__ W_ap2, const float* __restrict__ b_ap2,
                            const float* __restrict__ W_op2, const float* __restrict__ b_op2,
                            const float* __restrict__ W_reduc, const float* __restrict__ W_bi) {
    int idx = blockIdx.x * blockDim.x + threadIdx.x;
    const int T0 = RR * FP;
    const int T1 = T0 + N4 * KR2;
    const int T2 = T1 + N4 * KBI2;
    const int T3 = T2 + N4;
    if (idx < T0) {
        int n = idx / FP, k = idx - n * FP;
        float v = (k < FF) ? W_reduc[n * FF + k] : 0.f;
        g_Wrh[idx] = __float2half(v);
    } else if (idx < T1) {
        int i = idx - T0;
        int n = i / KR2, k = i - n * KR2;
        float v = 0.f;
        if (k < RR) {
            const float* src; int nn = n;
            if (n < HH)          { src = W_ap;  }
            else if (n < 2 * HH) { src = W_op;  nn = n - HH; }
            else if (n < 3 * HH) { src = W_ap2; nn = n - 2 * HH; }
            else                 { src = W_op2; nn = n - 3 * HH; }
            v = src[nn * RR + k];
        }
        g_Wch[i] = __float2half(v);
    } else if (idx < T2) {
        int i = idx - T1;
        int n = i / KBI2, k = i - n * KBI2;
        float v = (k < HH + 1) ? W_bi[n * (HH + 1) + k] : 0.f;
        g_Wbh[i] = __float2half(v);
    } else if (idx < T3) {
        int n = idx - T2;
        const float* src; int nn = n;
        if (n < HH)          { src = b_ap;  }
        else if (n < 2 * HH) { src = b_op;  nn = n - HH; }
        else if (n < 3 * HH) { src = b_ap2; nn = n - 2 * HH; }
        else                 { src = b_op2; nn = n - 3 * HH; }
        g_bcat[n] = src[nn];
    }
}

// set bias-1 column of in1
__global__ void init_kernel() {
    int w = blockIdx.x * blockDim.x + threadIdx.x;
    if (w < NW) {
        g_i1h[(long)w * KBI2 + HH] = __float2half(1.0f);
        g_i1l[(long)w * KBI2 + HH] = __float2half(0.0f);
    }
}

// ---------------- pool subwords + concat pos embedding -> f16 hi/lo ----------------
__global__ void pool_kernel(const float* __restrict__ bert,
                            const int* __restrict__ positions,
                            const int* __restrict__ postag,
                            const float* __restrict__ embed) {
    int idx = blockIdx.x * blockDim.x + threadIdx.x;
    if (idx >= NW * FP) return;
    int w = idx / FP;
    int f = idx - w * FP;
    float v = 0.f;
    if (f < PD) {
        v = embed[postag[w] * PD + f];
    } else if (f < FF) {
        int d  = f - PD;
        int s0 = positions[2 * w];
        int s1 = positions[2 * w + 1];
        int b  = w / LL;
        const float* base = bert + ((long)b * SS) * DD + d;
        float s = 0.f;
        for (int t = s0; t <= s1; t++) s += base[(long)t * DD];
        v = s / (float)(s1 - s0 + 1);
    }
    hsplit(v, &g_hh[idx], &g_hl[idx]);
}

// ---------------- tag heads (tiny) ----------------
__global__ void tag_kernel(const float* __restrict__ W_aptag, const float* __restrict__ b_aptag,
                           const float* __restrict__ W_optag, const float* __restrict__ b_optag,
                           float* __restrict__ out) {
    int idx = blockIdx.x * blockDim.x + threadIdx.x;
    if (idx >= NW * 10) return;
    int w = idx / 10, t = idx - w * 10;
    const float* rep;
    const float* wv;
    float acc;
    int off;
    if (t < NTAG) {
        rep = g_rep + (long)w * N4;
        wv  = W_aptag + t * HH;
        acc = b_aptag[t];
        off = OUT_AP_OFF + w * NTAG + t;
    } else {
        int tt = t - NTAG;
        rep = g_rep + (long)w * N4 + HH;
        wv  = W_optag + tt * HH;
        acc = b_optag[tt];
        off = OUT_OP_OFF + w * NTAG + tt;
    }
    #pragma unroll 5
    for (int k = 0; k < HH; k++) acc += rep[k] * wv[k];
    out[off] = acc;
}

// ---------------- launch ----------------
extern "C" void kernel_launch(void* const* d_in, const int* in_sizes, int n_in,
                              void* d_out, int out_size) {
    const float* bert      = (const float*)d_in[0];
    const int*   positions = (const int*)  d_in[1];
    const int*   postag    = (const int*)  d_in[2];
    const float* embed     = (const float*)d_in[3];
    const float* W_reduc   = (const float*)d_in[4];
    const float* b_reduc   = (const float*)d_in[5];
    const float* W_ap      = (const float*)d_in[6];
    const float* b_ap      = (const float*)d_in[7];
    const float* W_op      = (const float*)d_in[8];
    const float* b_op      = (const float*)d_in[9];
    const float* W_ap2     = (const float*)d_in[10];
    const float* b_ap2     = (const float*)d_in[11];
    const float* W_op2     = (const float*)d_in[12];
    const float* b_op2     = (const float*)d_in[13];
    const float* W_aptag   = (const float*)d_in[14];
    const float* b_aptag   = (const float*)d_in[15];
    const float* W_optag   = (const float*)d_in[16];
    const float* b_optag   = (const float*)d_in[17];
    const float* W_bi      = (const float*)d_in[18];
    float* out = (float*)d_out;

    void* p;
    cudaGetSymbolAddress(&p, g_hh);   f16* phh  = (f16*)p;
    cudaGetSymbolAddress(&p, g_hl);   f16* phl  = (f16*)p;
    cudaGetSymbolAddress(&p, g_rdh);  f16* prdh = (f16*)p;
    cudaGetSymbolAddress(&p, g_rdl);  f16* prdl = (f16*)p;
    cudaGetSymbolAddress(&p, g_i1h);  f16* pi1h = (f16*)p;
    cudaGetSymbolAddress(&p, g_i1l);  f16* pi1l = (f16*)p;
    cudaGetSymbolAddress(&p, g_onh);  f16* ponh = (f16*)p;
    cudaGetSymbolAddress(&p, g_onl);  f16* ponl = (f16*)p;
    cudaGetSymbolAddress(&p, g_afh);  f16* pafh = (f16*)p;
    cudaGetSymbolAddress(&p, g_Wrh);  f16* pWrh = (f16*)p;
    cudaGetSymbolAddress(&p, g_Wch);  f16* pWch = (f16*)p;
    cudaGetSymbolAddress(&p, g_Wbh);  f16* pWbh = (f16*)p;
    cudaGetSymbolAddress(&p, g_bcat); float* pbcat = (float*)p;

    cudaFuncSetAttribute(mma_gemm<0>, cudaFuncAttributeMaxDynamicSharedMemorySize, SMEM_SZ);
    cudaFuncSetAttribute(mma_gemm<1>, cudaFuncAttributeMaxDynamicSharedMemorySize, SMEM_SZ);
    cudaFuncSetAttribute(mma_gemm<2>, cudaFuncAttributeMaxDynamicSharedMemorySize, SMEM_SZ);
    cudaFuncSetAttribute(mma_gemm<3>, cudaFuncAttributeMaxDynamicSharedMemorySize, SMEM_SZ);

    // 1) pack weights + init bias column
    {
        int tot = RR * FP + N4 * KR2 + N4 * KBI2 + N4;
        pack_kernel<<<(tot + 255) / 256, 256>>>(W_ap, b_ap, W_op, b_op, W_ap2, b_ap2,
                                                W_op2, b_op2, W_reduc, W_bi);
        init_kernel<<<(NW + 255) / 256, 256>>>();
    }
    // 2) pool + concat -> f16 hi/lo
    {
        int tot = NW * FP;
        pool_kernel<<<(tot + 255) / 256, 256>>>(bert, positions, postag, embed);
    }
    // 3) gemm1: reduc = h @ Wr^T + b_reduc   M=25600, N=400, K=832 (26 chunks)
    {
        dim3 grid(7, NW / 128, 1);
        mma_gemm<0><<<grid, 256, SMEM_SZ>>>(phh, phl, FP, 0, pWrh, FP, 0,
                                            NW, RR, FP / 32, b_reduc, nullptr);
    }
    // 4) gemm2: rep = relu(reduc @ Wcat^T + bcat)  M=25600, N=600, K=416 (13 chunks)
    {
        dim3 grid(10, NW / 128, 1);
        mma_gemm<1><<<grid, 256, SMEM_SZ>>>(prdh, prdl, KR2, 0, pWch, KR2, 0,
                                            NW, N4, KR2 / 32, pbcat, nullptr);
    }
    // 5) tag heads
    {
        int tot = NW * 10;
        tag_kernel<<<(tot + 255) / 256, 256>>>(W_aptag, b_aptag, W_optag, b_optag, out);
    }
    // 6) affine = in1 @ Wbi^T   M=25600, N=600, K=160 (5 chunks)
    {
        dim3 grid(10, NW / 128, 1);
        mma_gemm<2><<<grid, 256, SMEM_SZ>>>(pi1h, pi1l, KBI2, 0, pWbh, KBI2, 0,
                                            NW, N4, KBI2 / 32, nullptr, nullptr);
    }
    // 7) tri: batched  M=200, N=800, K=160 per batch (5 chunks)
    {
        dim3 grid(13, 2, BB);
        mma_gemm<3><<<grid, 256, SMEM_SZ>>>(ponh, ponl, KBI2, (long)LL * KBI2,
                                            pafh, KBI2, (long)LL * 4 * KBI2,
                                            LL, KTRI, KBI2 / 32, nullptr, out);
    }
}